// round 1
// baseline (speedup 1.0000x reference)
#include <cuda_runtime.h>
#include <math.h>

// ----------------------------------------------------------------------------
// CrossAttention: q = x@Wq+bq; k,v = enc@W+b; scores = q k^T / sqrt(H);
// attn = softmax(scores); out = (attn @ v) @ Wp + bp
// B=8, T=S=1024, E=H=768. All fp32.
//
// Round 1: pure fp32 SIMT tiled GEMMs (128x128x16, 8x8 per thread, 4+4 split
// register layout) + block-per-row softmax. 6 launches, graph-capturable,
// scratch in __device__ globals.
// ----------------------------------------------------------------------------

#define BM 128
#define BN 128
#define BK 16

static const int Bb_ = 8, T_ = 1024, S_ = 1024, E_ = 768, H_ = 768;

__device__ float g_q[8 * 1024 * 768];
__device__ float g_k[8 * 1024 * 768];
__device__ float g_v[8 * 1024 * 768];
__device__ float g_scores[8 * 1024 * 1024];
__device__ float g_attnout[8 * 1024 * 768];

// ---------------------------------------------------------------------------
// NN GEMM: C[m,n] = alpha * sum_k A[m,k]*B[k,n] + bias[n]   (bias nullable)
// Batched via element strides sA,sB,sC (z = blockIdx.z).
// Requires M%128==0, N%128==0, K%16==0, N%4==0, K%4==0.
// ---------------------------------------------------------------------------
__global__ __launch_bounds__(256) void gemm_nn(
    const float* __restrict__ A, const float* __restrict__ B,
    const float* __restrict__ bias, float* __restrict__ C,
    int M, int N, int K, float alpha,
    long long sA, long long sB, long long sC)
{
    __shared__ float As[BK][BM];
    __shared__ float Bs[BK][BN];

    const int tid = threadIdx.x;
    const int tx = tid & 15;
    const int ty = tid >> 4;
    const long long z = blockIdx.z;
    const float* Ab = A + z * sA;
    const float* Bbp = B + z * sB;
    float* Cb = C + z * sC;
    const int row0 = blockIdx.y * BM;
    const int col0 = blockIdx.x * BN;

    float acc[8][8];
#pragma unroll
    for (int i = 0; i < 8; ++i)
#pragma unroll
        for (int j = 0; j < 8; ++j) acc[i][j] = 0.0f;

    for (int k0 = 0; k0 < K; k0 += BK) {
#pragma unroll
        for (int t = 0; t < 2; ++t) {
            int i = tid + t * 256;
            // A tile: 128 rows x 16 cols, 4 float4 per row
            int ar = i >> 2, ac4 = i & 3;
            float4 av = *(const float4*)(Ab + (long long)(row0 + ar) * K + k0 + ac4 * 4);
            As[ac4 * 4 + 0][ar] = av.x;
            As[ac4 * 4 + 1][ar] = av.y;
            As[ac4 * 4 + 2][ar] = av.z;
            As[ac4 * 4 + 3][ar] = av.w;
            // B tile: 16 rows x 128 cols, 32 float4 per row
            int br = i >> 5, bc4 = i & 31;
            float4 bv = *(const float4*)(Bbp + (long long)(k0 + br) * N + col0 + bc4 * 4);
            *(float4*)&Bs[br][bc4 * 4] = bv;
        }
        __syncthreads();

#pragma unroll
        for (int kk = 0; kk < BK; ++kk) {
            float a[8], b[8];
#pragma unroll
            for (int i = 0; i < 4; ++i) {
                a[i]     = As[kk][ty * 4 + i];
                a[i + 4] = As[kk][64 + ty * 4 + i];
                b[i]     = Bs[kk][tx * 4 + i];
                b[i + 4] = Bs[kk][64 + tx * 4 + i];
            }
#pragma unroll
            for (int i = 0; i < 8; ++i)
#pragma unroll
                for (int j = 0; j < 8; ++j)
                    acc[i][j] = fmaf(a[i], b[j], acc[i][j]);
        }
        __syncthreads();
    }

#pragma unroll
    for (int i = 0; i < 8; ++i) {
        int r = row0 + ((i < 4) ? (ty * 4 + i) : (64 + ty * 4 + (i - 4)));
#pragma unroll
        for (int jh = 0; jh < 2; ++jh) {
            int c = col0 + jh * 64 + tx * 4;
            float4 o;
            o.x = acc[i][jh * 4 + 0] * alpha;
            o.y = acc[i][jh * 4 + 1] * alpha;
            o.z = acc[i][jh * 4 + 2] * alpha;
            o.w = acc[i][jh * 4 + 3] * alpha;
            if (bias) {
                o.x += bias[c + 0];
                o.y += bias[c + 1];
                o.z += bias[c + 2];
                o.w += bias[c + 3];
            }
            *(float4*)(Cb + (long long)r * N + c) = o;
        }
    }
}

// ---------------------------------------------------------------------------
// NT GEMM: C[m,n] = alpha * sum_k A[m,k]*B[n,k]   (both row-major, K inner)
// ---------------------------------------------------------------------------
__global__ __launch_bounds__(256) void gemm_nt(
    const float* __restrict__ A, const float* __restrict__ B,
    float* __restrict__ C,
    int M, int N, int K, float alpha,
    long long sA, long long sB, long long sC)
{
    __shared__ float As[BK][BM];
    __shared__ float Bs[BK][BN];

    const int tid = threadIdx.x;
    const int tx = tid & 15;
    const int ty = tid >> 4;
    const long long z = blockIdx.z;
    const float* Ab = A + z * sA;
    const float* Bbp = B + z * sB;
    float* Cb = C + z * sC;
    const int row0 = blockIdx.y * BM;
    const int col0 = blockIdx.x * BN;

    float acc[8][8];
#pragma unroll
    for (int i = 0; i < 8; ++i)
#pragma unroll
        for (int j = 0; j < 8; ++j) acc[i][j] = 0.0f;

    for (int k0 = 0; k0 < K; k0 += BK) {
#pragma unroll
        for (int t = 0; t < 2; ++t) {
            int i = tid + t * 256;
            int ar = i >> 2, ac4 = i & 3;
            float4 av = *(const float4*)(Ab + (long long)(row0 + ar) * K + k0 + ac4 * 4);
            As[ac4 * 4 + 0][ar] = av.x;
            As[ac4 * 4 + 1][ar] = av.y;
            As[ac4 * 4 + 2][ar] = av.z;
            As[ac4 * 4 + 3][ar] = av.w;
            // B tile: rows col0..col0+127 of B[N,K], cols k0..k0+15 -> transpose
            int br = i >> 2, bc4 = i & 3;
            float4 bv = *(const float4*)(Bbp + (long long)(col0 + br) * K + k0 + bc4 * 4);
            Bs[bc4 * 4 + 0][br] = bv.x;
            Bs[bc4 * 4 + 1][br] = bv.y;
            Bs[bc4 * 4 + 2][br] = bv.z;
            Bs[bc4 * 4 + 3][br] = bv.w;
        }
        __syncthreads();

#pragma unroll
        for (int kk = 0; kk < BK; ++kk) {
            float a[8], b[8];
#pragma unroll
            for (int i = 0; i < 4; ++i) {
                a[i]     = As[kk][ty * 4 + i];
                a[i + 4] = As[kk][64 + ty * 4 + i];
                b[i]     = Bs[kk][tx * 4 + i];
                b[i + 4] = Bs[kk][64 + tx * 4 + i];
            }
#pragma unroll
            for (int i = 0; i < 8; ++i)
#pragma unroll
                for (int j = 0; j < 8; ++j)
                    acc[i][j] = fmaf(a[i], b[j], acc[i][j]);
        }
        __syncthreads();
    }

#pragma unroll
    for (int i = 0; i < 8; ++i) {
        int r = row0 + ((i < 4) ? (ty * 4 + i) : (64 + ty * 4 + (i - 4)));
#pragma unroll
        for (int jh = 0; jh < 2; ++jh) {
            int c = col0 + jh * 64 + tx * 4;
            float4 o;
            o.x = acc[i][jh * 4 + 0] * alpha;
            o.y = acc[i][jh * 4 + 1] * alpha;
            o.z = acc[i][jh * 4 + 2] * alpha;
            o.w = acc[i][jh * 4 + 3] * alpha;
            *(float4*)(Cb + (long long)r * N + c) = o;
        }
    }
}

// ---------------------------------------------------------------------------
// Row softmax over S=1024: one block (256 thr) per row, 4 elems/thread.
// ---------------------------------------------------------------------------
__global__ __launch_bounds__(256) void softmax_rows(float* __restrict__ s)
{
    const long long row = blockIdx.x;
    float* p = s + row * 1024;
    const int tid = threadIdx.x;

    float4 v = *(float4*)(p + tid * 4);

    __shared__ float red[8];

    // max
    float m = fmaxf(fmaxf(v.x, v.y), fmaxf(v.z, v.w));
#pragma unroll
    for (int o = 16; o > 0; o >>= 1) m = fmaxf(m, __shfl_xor_sync(0xffffffffu, m, o));
    if ((tid & 31) == 0) red[tid >> 5] = m;
    __syncthreads();
    float bm = red[0];
#pragma unroll
    for (int i = 1; i < 8; ++i) bm = fmaxf(bm, red[i]);
    __syncthreads();

    // exp + sum
    v.x = __expf(v.x - bm);
    v.y = __expf(v.y - bm);
    v.z = __expf(v.z - bm);
    v.w = __expf(v.w - bm);
    float sum = v.x + v.y + v.z + v.w;
#pragma unroll
    for (int o = 16; o > 0; o >>= 1) sum += __shfl_xor_sync(0xffffffffu, sum, o);
    if ((tid & 31) == 0) red[tid >> 5] = sum;
    __syncthreads();
    float bs = red[0];
#pragma unroll
    for (int i = 1; i < 8; ++i) bs += red[i];

    float inv = 1.0f / bs;
    v.x *= inv; v.y *= inv; v.z *= inv; v.w *= inv;
    *(float4*)(p + tid * 4) = v;
}

// ---------------------------------------------------------------------------
extern "C" void kernel_launch(void* const* d_in, const int* in_sizes, int n_in,
                              void* d_out, int out_size)
{
    const float* x   = (const float*)d_in[0];  // [B,T,E]
    const float* enc = (const float*)d_in[1];  // [B,S,E]
    const float* Wq  = (const float*)d_in[2];
    const float* bq  = (const float*)d_in[3];
    const float* Wk  = (const float*)d_in[4];
    const float* bk  = (const float*)d_in[5];
    const float* Wv  = (const float*)d_in[6];
    const float* bv  = (const float*)d_in[7];
    const float* Wp  = (const float*)d_in[8];
    const float* bp  = (const float*)d_in[9];
    float* out = (float*)d_out;

    float *q, *k, *v, *scores, *attnout;
    cudaGetSymbolAddress((void**)&q, g_q);
    cudaGetSymbolAddress((void**)&k, g_k);
    cudaGetSymbolAddress((void**)&v, g_v);
    cudaGetSymbolAddress((void**)&scores, g_scores);
    cudaGetSymbolAddress((void**)&attnout, g_attnout);

    const int BT = Bb_ * T_;   // 8192
    const float scale = 1.0f / sqrtf((float)H_);

    dim3 blk(256);

    // QKV projections: [8192,768] = [8192,768] @ [768,768] + bias
    dim3 gqkv(E_ / BN, BT / BM, 1);  // (6, 64)
    gemm_nn<<<gqkv, blk>>>(x,   Wq, bq, q, BT, H_, E_, 1.0f, 0, 0, 0);
    gemm_nn<<<gqkv, blk>>>(enc, Wk, bk, k, BT, H_, E_, 1.0f, 0, 0, 0);
    gemm_nn<<<gqkv, blk>>>(enc, Wv, bv, v, BT, H_, E_, 1.0f, 0, 0, 0);

    // scores[b] = q[b] @ k[b]^T * scale   [1024,1024] per batch
    dim3 gsc(S_ / BN, T_ / BM, Bb_);  // (8, 8, 8)
    gemm_nt<<<gsc, blk>>>(q, k, scores, T_, S_, H_, scale,
                          (long long)T_ * H_, (long long)S_ * H_,
                          (long long)T_ * S_);

    // softmax over last dim
    softmax_rows<<<Bb_ * T_, blk>>>(scores);

    // attnout[b] = attn[b] @ v[b]   [1024,768] per batch
    dim3 gav(H_ / BN, T_ / BM, Bb_);  // (6, 8, 8)
    gemm_nn<<<gav, blk>>>(scores, v, nullptr, attnout, T_, H_, S_, 1.0f,
                          (long long)T_ * S_, (long long)S_ * H_,
                          (long long)T_ * H_);

    // final projection: [8192,768] @ [768,768] + bp
    gemm_nn<<<gqkv, blk>>>(attnout, Wp, bp, out, BT, E_, H_, 1.0f, 0, 0, 0);
}

// round 3
// speedup vs baseline: 2.3209x; 2.3209x over previous
#include <cuda_runtime.h>
#include <cuda_bf16.h>
#include <math.h>
#include <stdint.h>

// ============================================================================
// CrossAttention on GB300 via bf16 mma.sync with 3-term error compensation.
//   C = A*B^T computed as A_hi*B_hi + A_hi*B_lo + A_lo*B_hi  (K -> 3K concat)
// All GEMMs in NT form (both operands K-major bf16). Tile 128x128, BK=64
// (128B SW128 rows), 3-stage cp.async pipeline, m16n8k16 HMMA.
// ============================================================================

static const int Bb_ = 8, T_ = 1024, S_ = 1024, E_ = 768, Hh_ = 768;

#define STG_BYTES 16384           // 128 rows x 128B
#define NSTG 3
#define DSMEM_BYTES (NSTG * 2 * STG_BYTES)

// fp32 scratch
__device__ float g_q[8 * 1024 * 768];
__device__ float g_k[8 * 1024 * 768];
__device__ float g_v[8 * 1024 * 768];
__device__ float g_scores[8 * 1024 * 1024];
// bf16 split scratch
__device__ __nv_bfloat16 g_xc[8192LL * 2304];
__device__ __nv_bfloat16 g_encc[8192LL * 2304];
__device__ __nv_bfloat16 g_qc[8192LL * 2304];
__device__ __nv_bfloat16 g_kc[8192LL * 2304];
__device__ __nv_bfloat16 g_vtc[8LL * 768 * 3072];
__device__ __nv_bfloat16 g_attnc[8192LL * 3072];
__device__ __nv_bfloat16 g_wqt[768LL * 2304];
__device__ __nv_bfloat16 g_wkt[768LL * 2304];
__device__ __nv_bfloat16 g_wvt[768LL * 2304];
__device__ __nv_bfloat16 g_wpt[768LL * 2304];

// ---------------------------------------------------------------------------
static __device__ __forceinline__ uint32_t smem_u32(const void* p) {
    return (uint32_t)__cvta_generic_to_shared((void*)p);
}
static __device__ __forceinline__ void cp_async16(uint32_t dst, const void* src) {
    asm volatile("cp.async.cg.shared.global [%0], [%1], 16;" :: "r"(dst), "l"(src) : "memory");
}
#define CP_COMMIT() asm volatile("cp.async.commit_group;" ::: "memory")
#define CP_WAIT2()  asm volatile("cp.async.wait_group 2;" ::: "memory")

static __device__ __forceinline__ uint32_t swz128(uint32_t off) {
    return off ^ ((off >> 3) & 0x70);
}

#define LDSM_X4(r0, r1, r2, r3, addr) \
    asm volatile("ldmatrix.sync.aligned.m8n8.x4.shared.b16 {%0,%1,%2,%3}, [%4];" \
        : "=r"(r0), "=r"(r1), "=r"(r2), "=r"(r3) : "r"(addr))

static __device__ __forceinline__ void mma16816(
    float* d, const uint32_t* a, uint32_t b0, uint32_t b1)
{
    asm volatile(
        "mma.sync.aligned.m16n8k16.row.col.f32.bf16.bf16.f32 "
        "{%0,%1,%2,%3}, {%4,%5,%6,%7}, {%8,%9}, {%0,%1,%2,%3};"
        : "+f"(d[0]), "+f"(d[1]), "+f"(d[2]), "+f"(d[3])
        : "r"(a[0]), "r"(a[1]), "r"(a[2]), "r"(a[3]), "r"(b0), "r"(b1));
}

// ---------------------------------------------------------------------------
// NT GEMM: C[m,n] = alpha * sum_k A[m,k]*B[n,k] (+ bias[n])
// A: [M,K3] bf16 row-major; B: [N,K3] bf16 row-major. M,N % 128 == 0,
// K3 % 64 == 0, K3/64 >= 2. Batched via blockIdx.z / element strides.
// ---------------------------------------------------------------------------
__global__ __launch_bounds__(256, 2)
void gemm_mma_nt(const __nv_bfloat16* __restrict__ A,
                 const __nv_bfloat16* __restrict__ B,
                 const float* __restrict__ bias,
                 float* __restrict__ C,
                 int M, int N, int K3, float alpha,
                 long long sA, long long sB, long long sC)
{
    extern __shared__ char dsmem_raw[];
    const uint32_t base = smem_u32(dsmem_raw);

    const int tid  = threadIdx.x;
    const int wid  = tid >> 5;
    const int lane = tid & 31;
    const int wm = wid & 3;          // warp row (32 rows each)
    const int wn = wid >> 2;         // warp col (64 cols each)
    const long long z = blockIdx.z;
    const int row0 = blockIdx.y * 128;
    const int col0 = blockIdx.x * 128;

    const __nv_bfloat16* Ab = A + z * sA + (long long)row0 * K3;
    const __nv_bfloat16* Bb = B + z * sB + (long long)col0 * K3;

    const int KI = K3 >> 6;

    // per-thread global->smem geometry: 4 x 16B chunks per operand per stage
    const int ldr0 = tid >> 3;       // row for i=0 (rows advance by 32)
    const int ldc  = tid & 7;        // 16B chunk

    // ldmatrix lane geometry
    const int g = lane >> 3;
    const int arow = wm * 32 + (g & 1) * 8 + (lane & 7);
    const int ach  = g >> 1;
    const int brow = wn * 64 + (g >> 1) * 8 + (lane & 7);
    const int bch  = g & 1;

    float acc[2][8][4];
#pragma unroll
    for (int t = 0; t < 2; ++t)
#pragma unroll
        for (int u = 0; u < 8; ++u)
#pragma unroll
            for (int r = 0; r < 4; ++r) acc[t][u][r] = 0.0f;

    // ---- stage loader ----
    auto load_stage = [&](int kb) {
        const uint32_t sa = base + (kb % NSTG) * STG_BYTES;
        const uint32_t sb = base + NSTG * STG_BYTES + (kb % NSTG) * STG_BYTES;
        const long long k0 = (long long)kb * 64 + ldc * 8;
#pragma unroll
        for (int i = 0; i < 4; ++i) {
            const int r = ldr0 + i * 32;
            const uint32_t so = swz128((uint32_t)(r * 128 + ldc * 16));
            cp_async16(sa + so, Ab + (long long)r * K3 + k0);
            cp_async16(sb + so, Bb + (long long)r * K3 + k0);
        }
    };

    load_stage(0); CP_COMMIT();
    load_stage(1); CP_COMMIT();

    for (int it = 0; it < KI; ++it) {
        if (it + 2 < KI) load_stage(it + 2);
        CP_COMMIT();
        CP_WAIT2();                  // stage `it` resident
        __syncthreads();

        const int s = it % NSTG;
        const uint32_t sa = base + s * STG_BYTES;
        const uint32_t sb = base + NSTG * STG_BYTES + s * STG_BYTES;

#pragma unroll
        for (int kk = 0; kk < 4; ++kk) {
            uint32_t af[2][4];
#pragma unroll
            for (int t = 0; t < 2; ++t) {
                const uint32_t ad = sa + swz128(
                    (uint32_t)((arow + t * 16) * 128 + (kk * 2 + ach) * 16));
                LDSM_X4(af[t][0], af[t][1], af[t][2], af[t][3], ad);
            }
            uint32_t bf[4][4];
#pragma unroll
            for (int p = 0; p < 4; ++p) {
                const uint32_t bd = sb + swz128(
                    (uint32_t)((brow + p * 16) * 128 + (kk * 2 + bch) * 16));
                LDSM_X4(bf[p][0], bf[p][1], bf[p][2], bf[p][3], bd);
            }
#pragma unroll
            for (int t = 0; t < 2; ++t)
#pragma unroll
                for (int u = 0; u < 8; ++u)
                    mma16816(acc[t][u], af[t],
                             bf[u >> 1][(u & 1) * 2], bf[u >> 1][(u & 1) * 2 + 1]);
        }
        __syncthreads();
    }

    // ---- epilogue ----
    float* Cz = C + z * sC;
#pragma unroll
    for (int t = 0; t < 2; ++t) {
        const int r_lo = row0 + wm * 32 + t * 16 + (lane >> 2);
#pragma unroll
        for (int u = 0; u < 8; ++u) {
            const int c = col0 + wn * 64 + u * 8 + 2 * (lane & 3);
            float b0 = 0.f, b1 = 0.f;
            if (bias) { b0 = bias[c]; b1 = bias[c + 1]; }
            float2 v0, v1;
            v0.x = acc[t][u][0] * alpha + b0;
            v0.y = acc[t][u][1] * alpha + b1;
            v1.x = acc[t][u][2] * alpha + b0;
            v1.y = acc[t][u][3] * alpha + b1;
            *(float2*)(Cz + (long long)r_lo * N + c) = v0;
            *(float2*)(Cz + (long long)(r_lo + 8) * N + c) = v1;
        }
    }
}

// ---------------------------------------------------------------------------
// fp32 [R,K] -> bf16 [R,3K] split. pattern 0: (hi,hi,lo); 1: (hi,lo,hi).
// ---------------------------------------------------------------------------
__global__ __launch_bounds__(256) void conv_split(
    const float* __restrict__ src, __nv_bfloat16* __restrict__ dst,
    int K, int pattern, long long total4)
{
    const long long i = (long long)blockIdx.x * 256 + threadIdx.x;
    if (i >= total4) return;
    const int Kq = K >> 2;
    const long long row = i / Kq;
    const int kq = (int)(i - row * Kq) << 2;

    const float4 v = *(const float4*)(src + i * 4);
    float f[4] = {v.x, v.y, v.z, v.w};
    __nv_bfloat16 h[4], l[4];
#pragma unroll
    for (int j = 0; j < 4; ++j) {
        h[j] = __float2bfloat16(f[j]);
        l[j] = __float2bfloat16(f[j] - __bfloat162float(h[j]));
    }
    union { __nv_bfloat16 b[4]; unsigned long long u; } ph, pl;
#pragma unroll
    for (int j = 0; j < 4; ++j) { ph.b[j] = h[j]; pl.b[j] = l[j]; }

    __nv_bfloat16* d0 = dst + row * 3LL * K + kq;
    *(unsigned long long*)(d0) = ph.u;
    *(unsigned long long*)(d0 + K) = pattern ? pl.u : ph.u;
    *(unsigned long long*)(d0 + 2 * K) = pattern ? ph.u : pl.u;
}

// ---------------------------------------------------------------------------
// fp32 [R,C] -> bf16 [C,3R] transposed split (batched).
// ---------------------------------------------------------------------------
__global__ __launch_bounds__(256) void convT_split(
    const float* __restrict__ src, __nv_bfloat16* __restrict__ dst,
    int R, int Csz, int pattern, long long sSrc, long long sDst)
{
    __shared__ float tile[32][33];
    const int b = blockIdx.z;
    const int c0 = blockIdx.x * 32;
    const int r0 = blockIdx.y * 32;
    const int tx = threadIdx.x & 31;
    const int ty = threadIdx.x >> 5;   // 0..7

    const float* Sp = src + (long long)b * sSrc;
#pragma unroll
    for (int j = 0; j < 4; ++j)
        tile[ty + j * 8][tx] = Sp[(long long)(r0 + ty + j * 8) * Csz + c0 + tx];
    __syncthreads();

    __nv_bfloat16* Dp = dst + (long long)b * sDst;
#pragma unroll
    for (int j = 0; j < 4; ++j) {
        const int c = c0 + ty + j * 8;
        const int r = r0 + tx;
        const float v = tile[tx][ty + j * 8];
        const __nv_bfloat16 h = __float2bfloat16(v);
        const __nv_bfloat16 l = __float2bfloat16(v - __bfloat162float(h));
        const long long base = (long long)c * 3 * R + r;
        Dp[base] = h;
        Dp[base + R] = pattern ? l : h;
        Dp[base + 2 * R] = pattern ? h : l;
    }
}

// ---------------------------------------------------------------------------
// Row softmax over 1024 elements: one block (256 thr) per row.
// ---------------------------------------------------------------------------
__global__ __launch_bounds__(256) void softmax_rows(float* __restrict__ s)
{
    const long long row = blockIdx.x;
    float* p = s + row * 1024;
    const int tid = threadIdx.x;

    float4 v = *(float4*)(p + tid * 4);
    __shared__ float red[8];

    float m = fmaxf(fmaxf(v.x, v.y), fmaxf(v.z, v.w));
#pragma unroll
    for (int o = 16; o > 0; o >>= 1) m = fmaxf(m, __shfl_xor_sync(0xffffffffu, m, o));
    if ((tid & 31) == 0) red[tid >> 5] = m;
    __syncthreads();
    float bm = red[0];
#pragma unroll
    for (int i = 1; i < 8; ++i) bm = fmaxf(bm, red[i]);
    __syncthreads();

    v.x = __expf(v.x - bm); v.y = __expf(v.y - bm);
    v.z = __expf(v.z - bm); v.w = __expf(v.w - bm);
    float sum = v.x + v.y + v.z + v.w;
#pragma unroll
    for (int o = 16; o > 0; o >>= 1) sum += __shfl_xor_sync(0xffffffffu, sum, o);
    if ((tid & 31) == 0) red[tid >> 5] = sum;
    __syncthreads();
    float bs = red[0];
#pragma unroll
    for (int i = 1; i < 8; ++i) bs += red[i];

    const float inv = 1.0f / bs;
    v.x *= inv; v.y *= inv; v.z *= inv; v.w *= inv;
    *(float4*)(p + tid * 4) = v;
}

// ---------------------------------------------------------------------------
extern "C" void kernel_launch(void* const* d_in, const int* in_sizes, int n_in,
                              void* d_out, int out_size)
{
    const float* x   = (const float*)d_in[0];
    const float* enc = (const float*)d_in[1];
    const float* Wq  = (const float*)d_in[2];
    const float* bq  = (const float*)d_in[3];
    const float* Wk  = (const float*)d_in[4];
    const float* bk  = (const float*)d_in[5];
    const float* Wv  = (const float*)d_in[6];
    const float* bv  = (const float*)d_in[7];
    const float* Wp  = (const float*)d_in[8];
    const float* bp  = (const float*)d_in[9];
    float* out = (float*)d_out;

    float *q, *k, *v, *scores;
    __nv_bfloat16 *xc, *encc, *qc, *kc, *vtc, *attnc, *wqt, *wkt, *wvt, *wpt;
    cudaGetSymbolAddress((void**)&q, g_q);
    cudaGetSymbolAddress((void**)&k, g_k);
    cudaGetSymbolAddress((void**)&v, g_v);
    cudaGetSymbolAddress((void**)&scores, g_scores);
    cudaGetSymbolAddress((void**)&xc, g_xc);
    cudaGetSymbolAddress((void**)&encc, g_encc);
    cudaGetSymbolAddress((void**)&qc, g_qc);
    cudaGetSymbolAddress((void**)&kc, g_kc);
    cudaGetSymbolAddress((void**)&vtc, g_vtc);
    cudaGetSymbolAddress((void**)&attnc, g_attnc);
    cudaGetSymbolAddress((void**)&wqt, g_wqt);
    cudaGetSymbolAddress((void**)&wkt, g_wkt);
    cudaGetSymbolAddress((void**)&wvt, g_wvt);
    cudaGetSymbolAddress((void**)&wpt, g_wpt);

    cudaFuncSetAttribute(gemm_mma_nt,
                         cudaFuncAttributeMaxDynamicSharedMemorySize, DSMEM_BYTES);

    const int BT = Bb_ * T_;                 // 8192
    const float scale = 1.0f / sqrtf((float)Hh_);
    dim3 blk(256);

    // 1. Weight transposes+splits (pattern B)
    {
        dim3 g(E_ / 32, E_ / 32, 1);
        convT_split<<<g, blk>>>(Wq, wqt, E_, Hh_, 1, 0, 0);
        convT_split<<<g, blk>>>(Wk, wkt, E_, Hh_, 1, 0, 0);
        convT_split<<<g, blk>>>(Wv, wvt, E_, Hh_, 1, 0, 0);
        convT_split<<<g, blk>>>(Wp, wpt, Hh_, E_, 1, 0, 0);
    }

    // 2. Activation splits (pattern A)
    {
        long long t4 = (long long)BT * E_ / 4;
        conv_split<<<(unsigned)((t4 + 255) / 256), blk>>>(x, xc, E_, 0, t4);
        conv_split<<<(unsigned)((t4 + 255) / 256), blk>>>(enc, encc, E_, 0, t4);
    }

    // 3. QKV projections: [8192,768] fp32
    {
        dim3 g(Hh_ / 128, BT / 128, 1);
        gemm_mma_nt<<<g, blk, DSMEM_BYTES>>>(xc,   wqt, bq, q, BT, Hh_, 3 * E_, 1.0f, 0, 0, 0);
        gemm_mma_nt<<<g, blk, DSMEM_BYTES>>>(encc, wkt, bk, k, BT, Hh_, 3 * E_, 1.0f, 0, 0, 0);
        gemm_mma_nt<<<g, blk, DSMEM_BYTES>>>(encc, wvt, bv, v, BT, Hh_, 3 * E_, 1.0f, 0, 0, 0);
    }

    // 4. Split q (A), k (B); transpose+split v (B) per batch
    {
        long long t4 = (long long)BT * Hh_ / 4;
        conv_split<<<(unsigned)((t4 + 255) / 256), blk>>>(q, qc, Hh_, 0, t4);
        conv_split<<<(unsigned)((t4 + 255) / 256), blk>>>(k, kc, Hh_, 1, t4);
        dim3 gT(Hh_ / 32, S_ / 32, Bb_);
        convT_split<<<gT, blk>>>(v, vtc, S_, Hh_, 1,
                                 (long long)S_ * Hh_, (long long)Hh_ * 3 * S_);
    }

    // 5. scores[b] = q[b] k[b]^T * scale
    {
        dim3 g(S_ / 128, T_ / 128, Bb_);
        gemm_mma_nt<<<g, blk, DSMEM_BYTES>>>(qc, kc, nullptr, scores,
                                             T_, S_, 3 * Hh_, scale,
                                             (long long)T_ * 3 * Hh_,
                                             (long long)S_ * 3 * Hh_,
                                             (long long)T_ * S_);
    }

    // 6. softmax
    softmax_rows<<<BT, blk>>>(scores);

    // 7. split attn (A)
    {
        long long t4 = (long long)BT * S_ / 4;
        conv_split<<<(unsigned)((t4 + 255) / 256), blk>>>(scores, attnc, S_, 0, t4);
    }

    // 8. attnout[b] = attn[b] @ v[b]  -> reuse g_q as fp32 attnout
    {
        dim3 g(Hh_ / 128, T_ / 128, Bb_);
        gemm_mma_nt<<<g, blk, DSMEM_BYTES>>>(attnc, vtc, nullptr, q,
                                             T_, Hh_, 3 * S_, 1.0f,
                                             (long long)T_ * 3 * S_,
                                             (long long)Hh_ * 3 * S_,
                                             (long long)T_ * Hh_);
    }

    // 9. split attnout (A) -> reuse xc
    {
        long long t4 = (long long)BT * Hh_ / 4;
        conv_split<<<(unsigned)((t4 + 255) / 256), blk>>>(q, xc, Hh_, 0, t4);
    }

    // 10. out = attnout @ Wp + bp
    {
        dim3 g(E_ / 128, BT / 128, 1);
        gemm_mma_nt<<<g, blk, DSMEM_BYTES>>>(xc, wpt, bp, out, BT, E_, 3 * Hh_, 1.0f, 0, 0, 0);
    }
}

// round 4
// speedup vs baseline: 2.3841x; 1.0272x over previous
#include <cuda_runtime.h>
#include <cuda_bf16.h>
#include <math.h>
#include <stdint.h>

// ============================================================================
// CrossAttention via bf16 mma.sync + 3-term error compensation.
//   C = A*B^T ~= A_hi*B_hh + A_hi*B_lo + A_lo*B_hi   (K -> 3K concat)
// GEMMs in NT form. 128x128 tile, BK=64 (SW128 rows), 3-stage cp.async,
// m16n8k16 HMMA. Splits fused into GEMM epilogues and softmax.
// ============================================================================

static const int Bb_ = 8, T_ = 1024, S_ = 1024, E_ = 768, Hh_ = 768;

#define STG_BYTES 16384           // 128 rows x 128B
#define NSTG 3
#define DSMEM_BYTES (NSTG * 2 * STG_BYTES)

// scratch
__device__ float g_v[8 * 1024 * 768];
__device__ float g_scores[8 * 1024 * 1024];
__device__ __nv_bfloat16 g_xc[8192LL * 2304];     // x split; later attnout split
__device__ __nv_bfloat16 g_encc[8192LL * 2304];
__device__ __nv_bfloat16 g_qc[8192LL * 2304];
__device__ __nv_bfloat16 g_kc[8192LL * 2304];
__device__ __nv_bfloat16 g_vtc[8LL * 768 * 3072];
__device__ __nv_bfloat16 g_attnc[8192LL * 3072];
__device__ __nv_bfloat16 g_wqt[768LL * 2304];
__device__ __nv_bfloat16 g_wkt[768LL * 2304];
__device__ __nv_bfloat16 g_wvt[768LL * 2304];
__device__ __nv_bfloat16 g_wpt[768LL * 2304];

// ---------------------------------------------------------------------------
static __device__ __forceinline__ uint32_t smem_u32(const void* p) {
    return (uint32_t)__cvta_generic_to_shared((void*)p);
}
static __device__ __forceinline__ void cp_async16(uint32_t dst, const void* src) {
    asm volatile("cp.async.cg.shared.global [%0], [%1], 16;" :: "r"(dst), "l"(src) : "memory");
}
#define CP_COMMIT() asm volatile("cp.async.commit_group;" ::: "memory")
#define CP_WAIT2()  asm volatile("cp.async.wait_group 2;" ::: "memory")

static __device__ __forceinline__ uint32_t swz128(uint32_t off) {
    return off ^ ((off >> 3) & 0x70);
}

#define LDSM_X4(r0, r1, r2, r3, addr) \
    asm volatile("ldmatrix.sync.aligned.m8n8.x4.shared.b16 {%0,%1,%2,%3}, [%4];" \
        : "=r"(r0), "=r"(r1), "=r"(r2), "=r"(r3) : "r"(addr))

static __device__ __forceinline__ void mma16816(
    float* d, const uint32_t* a, uint32_t b0, uint32_t b1)
{
    asm volatile(
        "mma.sync.aligned.m16n8k16.row.col.f32.bf16.bf16.f32 "
        "{%0,%1,%2,%3}, {%4,%5,%6,%7}, {%8,%9}, {%0,%1,%2,%3};"
        : "+f"(d[0]), "+f"(d[1]), "+f"(d[2]), "+f"(d[3])
        : "r"(a[0]), "r"(a[1]), "r"(a[2]), "r"(a[3]), "r"(b0), "r"(b1));
}

// pack two fp32 into bf16x2 hi-parts and lo-parts
static __device__ __forceinline__ void split2(float x, float y, uint32_t& hh, uint32_t& ll) {
    __nv_bfloat16 hx = __float2bfloat16(x);
    __nv_bfloat16 hy = __float2bfloat16(y);
    __nv_bfloat16 lx = __float2bfloat16(x - __bfloat162float(hx));
    __nv_bfloat16 ly = __float2bfloat16(y - __bfloat162float(hy));
    hh = ((uint32_t)__bfloat16_as_ushort(hy) << 16) | __bfloat16_as_ushort(hx);
    ll = ((uint32_t)__bfloat16_as_ushort(ly) << 16) | __bfloat16_as_ushort(lx);
}

// ---------------------------------------------------------------------------
// NT GEMM: out = alpha * A @ B^T (+ bias).
// A: [M,K3] bf16 row-major; B: [N,K3] bf16 row-major. M,N % 128 == 0,
// K3 % 64 == 0. Batched via blockIdx.z.
// mode 0: write fp32 C [M,N] (stride sOut per batch).
// mode 1: write bf16 D [M,3N], slices (hi,hi,lo)   (pattern A)
// mode 2: write bf16 D [M,3N], slices (hi,lo,hi)   (pattern B)
// ---------------------------------------------------------------------------
__global__ __launch_bounds__(256, 2)
void gemm_mma_nt(const __nv_bfloat16* __restrict__ A,
                 const __nv_bfloat16* __restrict__ B,
                 const float* __restrict__ bias,
                 float* __restrict__ C,
                 __nv_bfloat16* __restrict__ D,
                 int mode,
                 int M, int N, int K3, float alpha,
                 long long sA, long long sB, long long sOut)
{
    extern __shared__ char dsmem_raw[];
    const uint32_t base = smem_u32(dsmem_raw);

    const int tid  = threadIdx.x;
    const int wid  = tid >> 5;
    const int lane = tid & 31;
    const int wm = wid & 3;
    const int wn = wid >> 2;
    const long long z = blockIdx.z;
    const int row0 = blockIdx.y * 128;
    const int col0 = blockIdx.x * 128;

    const __nv_bfloat16* Ab = A + z * sA + (long long)row0 * K3;
    const __nv_bfloat16* Bb = B + z * sB + (long long)col0 * K3;

    const int KI = K3 >> 6;

    const int ldr0 = tid >> 3;
    const int ldc  = tid & 7;

    const int g = lane >> 3;
    const int arow = wm * 32 + (g & 1) * 8 + (lane & 7);
    const int ach  = g >> 1;
    const int brow = wn * 64 + (g >> 1) * 8 + (lane & 7);
    const int bch  = g & 1;

    float acc[2][8][4];
#pragma unroll
    for (int t = 0; t < 2; ++t)
#pragma unroll
        for (int u = 0; u < 8; ++u)
#pragma unroll
            for (int r = 0; r < 4; ++r) acc[t][u][r] = 0.0f;

    auto load_stage = [&](int kb) {
        const uint32_t sa = base + (kb % NSTG) * STG_BYTES;
        const uint32_t sb = base + NSTG * STG_BYTES + (kb % NSTG) * STG_BYTES;
        const long long k0 = (long long)kb * 64 + ldc * 8;
#pragma unroll
        for (int i = 0; i < 4; ++i) {
            const int r = ldr0 + i * 32;
            const uint32_t so = swz128((uint32_t)(r * 128 + ldc * 16));
            cp_async16(sa + so, Ab + (long long)r * K3 + k0);
            cp_async16(sb + so, Bb + (long long)r * K3 + k0);
        }
    };

    load_stage(0); CP_COMMIT();
    load_stage(1); CP_COMMIT();

    for (int it = 0; it < KI; ++it) {
        if (it + 2 < KI) load_stage(it + 2);
        CP_COMMIT();
        CP_WAIT2();
        __syncthreads();

        const int s = it % NSTG;
        const uint32_t sa = base + s * STG_BYTES;
        const uint32_t sb = base + NSTG * STG_BYTES + s * STG_BYTES;

#pragma unroll
        for (int kk = 0; kk < 4; ++kk) {
            uint32_t af[2][4];
#pragma unroll
            for (int t = 0; t < 2; ++t) {
                const uint32_t ad = sa + swz128(
                    (uint32_t)((arow + t * 16) * 128 + (kk * 2 + ach) * 16));
                LDSM_X4(af[t][0], af[t][1], af[t][2], af[t][3], ad);
            }
            uint32_t bf[4][4];
#pragma unroll
            for (int p = 0; p < 4; ++p) {
                const uint32_t bd = sb + swz128(
                    (uint32_t)((brow + p * 16) * 128 + (kk * 2 + bch) * 16));
                LDSM_X4(bf[p][0], bf[p][1], bf[p][2], bf[p][3], bd);
            }
#pragma unroll
            for (int t = 0; t < 2; ++t)
#pragma unroll
                for (int u = 0; u < 8; ++u)
                    mma16816(acc[t][u], af[t],
                             bf[u >> 1][(u & 1) * 2], bf[u >> 1][(u & 1) * 2 + 1]);
        }
        __syncthreads();
    }

    // ---- epilogue ----
    if (mode == 0) {
        float* Cz = C + z * sOut;
#pragma unroll
        for (int t = 0; t < 2; ++t) {
            const int r_lo = row0 + wm * 32 + t * 16 + (lane >> 2);
#pragma unroll
            for (int u = 0; u < 8; ++u) {
                const int c = col0 + wn * 64 + u * 8 + 2 * (lane & 3);
                float b0 = 0.f, b1 = 0.f;
                if (bias) { b0 = bias[c]; b1 = bias[c + 1]; }
                float2 v0, v1;
                v0.x = acc[t][u][0] * alpha + b0;
                v0.y = acc[t][u][1] * alpha + b1;
                v1.x = acc[t][u][2] * alpha + b0;
                v1.y = acc[t][u][3] * alpha + b1;
                *(float2*)(Cz + (long long)r_lo * N + c) = v0;
                *(float2*)(Cz + (long long)(r_lo + 8) * N + c) = v1;
            }
        }
    } else {
        __nv_bfloat16* Dz = D + z * sOut;
        const int N3 = 3 * N;
#pragma unroll
        for (int t = 0; t < 2; ++t) {
            const int r_lo = row0 + wm * 32 + t * 16 + (lane >> 2);
#pragma unroll
            for (int u = 0; u < 8; ++u) {
                const int c = col0 + wn * 64 + u * 8 + 2 * (lane & 3);
                float b0 = 0.f, b1 = 0.f;
                if (bias) { b0 = bias[c]; b1 = bias[c + 1]; }
#pragma unroll
                for (int half = 0; half < 2; ++half) {
                    const int r = r_lo + half * 8;
                    const float vx = acc[t][u][half * 2 + 0] * alpha + b0;
                    const float vy = acc[t][u][half * 2 + 1] * alpha + b1;
                    uint32_t hh, ll;
                    split2(vx, vy, hh, ll);
                    uint32_t* p0 = (uint32_t*)(Dz + (long long)r * N3 + c);
                    p0[0] = hh;
                    *(uint32_t*)(Dz + (long long)r * N3 + N + c)     = (mode == 1) ? hh : ll;
                    *(uint32_t*)(Dz + (long long)r * N3 + 2 * N + c) = (mode == 1) ? ll : hh;
                }
            }
        }
    }
}

// ---------------------------------------------------------------------------
// fp32 [R,K] -> bf16 [R,3K] split, 8 elems/thread. pattern A (hi,hi,lo).
// ---------------------------------------------------------------------------
__global__ __launch_bounds__(256) void conv_split8(
    const float* __restrict__ src, __nv_bfloat16* __restrict__ dst,
    int K, long long total8)
{
    const long long i = (long long)blockIdx.x * 256 + threadIdx.x;
    if (i >= total8) return;
    const int K8 = K >> 3;
    const long long row = i / K8;
    const int k0 = (int)(i - row * K8) << 3;

    const float4 va = *(const float4*)(src + row * K + k0);
    const float4 vb = *(const float4*)(src + row * K + k0 + 4);
    float f[8] = {va.x, va.y, va.z, va.w, vb.x, vb.y, vb.z, vb.w};
    uint32_t hh[4], ll[4];
#pragma unroll
    for (int j = 0; j < 4; ++j) split2(f[2 * j], f[2 * j + 1], hh[j], ll[j]);

    uint4 H = make_uint4(hh[0], hh[1], hh[2], hh[3]);
    uint4 L = make_uint4(ll[0], ll[1], ll[2], ll[3]);
    __nv_bfloat16* d0 = dst + row * 3LL * K + k0;
    *(uint4*)(d0)         = H;
    *(uint4*)(d0 + K)     = H;
    *(uint4*)(d0 + 2 * K) = L;
}

// ---------------------------------------------------------------------------
// Transposed split: src fp32 [R,C] -> dst bf16 [C,3R], pattern B (hi,lo,hi).
// 8B stores (4 consecutive rows per thread). Batched over z.
// ---------------------------------------------------------------------------
static __device__ __forceinline__ void convT_tile(
    const float* __restrict__ Sp, __nv_bfloat16* __restrict__ Dp,
    int R, int Csz, int r0, int c0, int tid, float* tile /*32*33*/)
{
    const int tx = tid & 31;
    const int ty = tid >> 5;
#pragma unroll
    for (int j = 0; j < 4; ++j)
        tile[(ty + j * 8) * 33 + tx] = Sp[(long long)(r0 + ty + j * 8) * Csz + c0 + tx];
    __syncthreads();

    const int cl = tid >> 3;          // 0..31
    const int rs = (tid & 7) * 4;     // 0,4,...,28
    union { __nv_bfloat16 b[4]; unsigned long long u; } H, L;
#pragma unroll
    for (int j = 0; j < 4; ++j) {
        const float v = tile[(rs + j) * 33 + cl];
        H.b[j] = __float2bfloat16(v);
        L.b[j] = __float2bfloat16(v - __bfloat162float(H.b[j]));
    }
    const long long basee = (long long)(c0 + cl) * 3 * R + (r0 + rs);
    *(unsigned long long*)(Dp + basee)         = H.u;
    *(unsigned long long*)(Dp + basee + R)     = L.u;
    *(unsigned long long*)(Dp + basee + 2 * R) = H.u;
}

__global__ __launch_bounds__(256) void convT_split(
    const float* __restrict__ src, __nv_bfloat16* __restrict__ dst,
    int R, int Csz, long long sSrc, long long sDst)
{
    __shared__ float tile[32 * 33];
    const int b = blockIdx.z;
    convT_tile(src + (long long)b * sSrc, dst + (long long)b * sDst,
               R, Csz, blockIdx.y * 32, blockIdx.x * 32, threadIdx.x, tile);
}

// Four weight matrices in one launch (all 768x768, pattern B).
__global__ __launch_bounds__(256) void convT_split_w(
    const float* __restrict__ s0, const float* __restrict__ s1,
    const float* __restrict__ s2, const float* __restrict__ s3,
    __nv_bfloat16* __restrict__ d0, __nv_bfloat16* __restrict__ d1,
    __nv_bfloat16* __restrict__ d2, __nv_bfloat16* __restrict__ d3,
    int R, int Csz)
{
    __shared__ float tile[32 * 33];
    const float* s = (blockIdx.z == 0) ? s0 : (blockIdx.z == 1) ? s1
                   : (blockIdx.z == 2) ? s2 : s3;
    __nv_bfloat16* d = (blockIdx.z == 0) ? d0 : (blockIdx.z == 1) ? d1
                     : (blockIdx.z == 2) ? d2 : d3;
    convT_tile(s, d, R, Csz, blockIdx.y * 32, blockIdx.x * 32, threadIdx.x, tile);
}

// ---------------------------------------------------------------------------
// Fused softmax + split: read scores fp32 row [1024], write bf16 [3*1024]
// pattern A (hi,hi,lo). One block (256 thr) per row.
// ---------------------------------------------------------------------------
__global__ __launch_bounds__(256) void softmax_split(
    const float* __restrict__ s, __nv_bfloat16* __restrict__ dst)
{
    const long long row = blockIdx.x;
    const float* p = s + row * 1024;
    const int tid = threadIdx.x;

    float4 v = *(const float4*)(p + tid * 4);
    __shared__ float red[8];

    float m = fmaxf(fmaxf(v.x, v.y), fmaxf(v.z, v.w));
#pragma unroll
    for (int o = 16; o > 0; o >>= 1) m = fmaxf(m, __shfl_xor_sync(0xffffffffu, m, o));
    if ((tid & 31) == 0) red[tid >> 5] = m;
    __syncthreads();
    float bm = red[0];
#pragma unroll
    for (int i = 1; i < 8; ++i) bm = fmaxf(bm, red[i]);
    __syncthreads();

    v.x = __expf(v.x - bm); v.y = __expf(v.y - bm);
    v.z = __expf(v.z - bm); v.w = __expf(v.w - bm);
    float sum = v.x + v.y + v.z + v.w;
#pragma unroll
    for (int o = 16; o > 0; o >>= 1) sum += __shfl_xor_sync(0xffffffffu, sum, o);
    if ((tid & 31) == 0) red[tid >> 5] = sum;
    __syncthreads();
    float bs = red[0];
#pragma unroll
    for (int i = 1; i < 8; ++i) bs += red[i];

    const float inv = 1.0f / bs;
    v.x *= inv; v.y *= inv; v.z *= inv; v.w *= inv;

    uint32_t h0, l0, h1, l1;
    split2(v.x, v.y, h0, l0);
    split2(v.z, v.w, h1, l1);
    uint2 H = make_uint2(h0, h1);
    uint2 L = make_uint2(l0, l1);
    __nv_bfloat16* d0 = dst + row * 3072 + tid * 4;
    *(uint2*)(d0)        = H;
    *(uint2*)(d0 + 1024) = H;
    *(uint2*)(d0 + 2048) = L;
}

// ---------------------------------------------------------------------------
extern "C" void kernel_launch(void* const* d_in, const int* in_sizes, int n_in,
                              void* d_out, int out_size)
{
    const float* x   = (const float*)d_in[0];
    const float* enc = (const float*)d_in[1];
    const float* Wq  = (const float*)d_in[2];
    const float* bq  = (const float*)d_in[3];
    const float* Wk  = (const float*)d_in[4];
    const float* bk  = (const float*)d_in[5];
    const float* Wv  = (const float*)d_in[6];
    const float* bv  = (const float*)d_in[7];
    const float* Wp  = (const float*)d_in[8];
    const float* bp  = (const float*)d_in[9];
    float* out = (float*)d_out;

    float *v, *scores;
    __nv_bfloat16 *xc, *encc, *qc, *kc, *vtc, *attnc, *wqt, *wkt, *wvt, *wpt;
    cudaGetSymbolAddress((void**)&v, g_v);
    cudaGetSymbolAddress((void**)&scores, g_scores);
    cudaGetSymbolAddress((void**)&xc, g_xc);
    cudaGetSymbolAddress((void**)&encc, g_encc);
    cudaGetSymbolAddress((void**)&qc, g_qc);
    cudaGetSymbolAddress((void**)&kc, g_kc);
    cudaGetSymbolAddress((void**)&vtc, g_vtc);
    cudaGetSymbolAddress((void**)&attnc, g_attnc);
    cudaGetSymbolAddress((void**)&wqt, g_wqt);
    cudaGetSymbolAddress((void**)&wkt, g_wkt);
    cudaGetSymbolAddress((void**)&wvt, g_wvt);
    cudaGetSymbolAddress((void**)&wpt, g_wpt);

    cudaFuncSetAttribute(gemm_mma_nt,
                         cudaFuncAttributeMaxDynamicSharedMemorySize, DSMEM_BYTES);

    const int BT = Bb_ * T_;                 // 8192
    const float scale = 1.0f / sqrtf((float)Hh_);
    dim3 blk(256);

    // 1. All four weight transposes+splits in one launch (pattern B)
    {
        dim3 g(E_ / 32, E_ / 32, 4);
        convT_split_w<<<g, blk>>>(Wq, Wk, Wv, Wp, wqt, wkt, wvt, wpt, E_, Hh_);
    }

    // 2. Activation splits (pattern A)
    {
        long long t8 = (long long)BT * E_ / 8;
        conv_split8<<<(unsigned)((t8 + 255) / 256), blk>>>(x, xc, E_, t8);
        conv_split8<<<(unsigned)((t8 + 255) / 256), blk>>>(enc, encc, E_, t8);
    }

    // 3. QKV projections — q,k write split directly; v stays fp32
    {
        dim3 g(Hh_ / 128, BT / 128, 1);
        gemm_mma_nt<<<g, blk, DSMEM_BYTES>>>(xc,   wqt, bq, nullptr, qc, 1,
                                             BT, Hh_, 3 * E_, 1.0f, 0, 0, 0);
        gemm_mma_nt<<<g, blk, DSMEM_BYTES>>>(encc, wkt, bk, nullptr, kc, 2,
                                             BT, Hh_, 3 * E_, 1.0f, 0, 0, 0);
        gemm_mma_nt<<<g, blk, DSMEM_BYTES>>>(encc, wvt, bv, v, nullptr, 0,
                                             BT, Hh_, 3 * E_, 1.0f, 0, 0, 0);
    }

    // 4. v transpose+split (pattern B), per batch
    {
        dim3 gT(Hh_ / 32, S_ / 32, Bb_);
        convT_split<<<gT, blk>>>(v, vtc, S_, Hh_,
                                 (long long)S_ * Hh_, (long long)Hh_ * 3 * S_);
    }

    // 5. scores[b] = q[b] k[b]^T * scale  (fp32)
    {
        dim3 g(S_ / 128, T_ / 128, Bb_);
        gemm_mma_nt<<<g, blk, DSMEM_BYTES>>>(qc, kc, nullptr, scores, nullptr, 0,
                                             T_, S_, 3 * Hh_, scale,
                                             (long long)T_ * 3 * Hh_,
                                             (long long)S_ * 3 * Hh_,
                                             (long long)T_ * S_);
    }

    // 6. softmax + split (pattern A) -> attnc
    softmax_split<<<BT, blk>>>(scores, attnc);

    // 7. attnout[b] = attn[b] @ v[b], split written directly (pattern A) -> xc
    {
        dim3 g(Hh_ / 128, T_ / 128, Bb_);
        gemm_mma_nt<<<g, blk, DSMEM_BYTES>>>(attnc, vtc, nullptr, nullptr, xc, 1,
                                             T_, Hh_, 3 * S_, 1.0f,
                                             (long long)T_ * 3 * S_,
                                             (long long)Hh_ * 3 * S_,
                                             (long long)T_ * 3 * Hh_);
    }

    // 8. out = attnout @ Wp + bp  (fp32)
    {
        dim3 g(E_ / 128, BT / 128, 1);
        gemm_mma_nt<<<g, blk, DSMEM_BYTES>>>(xc, wpt, bp, out, nullptr, 0,
                                             BT, E_, 3 * Hh_, 1.0f, 0, 0, 0);
    }
}

// round 5
// speedup vs baseline: 2.5018x; 1.0494x over previous
#include <cuda_runtime.h>
#include <cuda_bf16.h>
#include <math.h>
#include <stdint.h>

// ============================================================================
// CrossAttention via bf16 mma.sync + 3-term error compensation.
//   C = A*B^T ~= A_hi*B_hi + A_hi*B_lo + A_lo*B_hi   (K -> 3K concat)
// GEMMs in NT form. 128x128 tile, BK=64 (SW128 rows), 3-stage cp.async,
// ONE __syncthreads per K-iter. Splits fused into epilogues / softmax.
// V^T produced directly by GEMM (row-bias) — no fp32 V, no transpose pass.
// ============================================================================

static const int Bb_ = 8, T_ = 1024, S_ = 1024, E_ = 768, Hh_ = 768;

#define STG_BYTES 16384           // 128 rows x 128B
#define NSTG 3
#define DSMEM_BYTES (NSTG * 2 * STG_BYTES)

// scratch
__device__ float g_scores[8 * 1024 * 1024];
__device__ __nv_bfloat16 g_xc[8192LL * 2304];     // x split; later attnout split
__device__ __nv_bfloat16 g_encc[8192LL * 2304];
__device__ __nv_bfloat16 g_qc[8192LL * 2304];
__device__ __nv_bfloat16 g_kc[8192LL * 2304];
__device__ __nv_bfloat16 g_vtc[8LL * 768 * 3072];
__device__ __nv_bfloat16 g_attnc[8192LL * 3072];
__device__ __nv_bfloat16 g_wqt[768LL * 2304];
__device__ __nv_bfloat16 g_wkt[768LL * 2304];
__device__ __nv_bfloat16 g_wvt[768LL * 2304];
__device__ __nv_bfloat16 g_wpt[768LL * 2304];

// ---------------------------------------------------------------------------
static __device__ __forceinline__ uint32_t smem_u32(const void* p) {
    return (uint32_t)__cvta_generic_to_shared((void*)p);
}
static __device__ __forceinline__ void cp_async16(uint32_t dst, const void* src) {
    asm volatile("cp.async.cg.shared.global [%0], [%1], 16;" :: "r"(dst), "l"(src) : "memory");
}
#define CP_COMMIT() asm volatile("cp.async.commit_group;" ::: "memory")
#define CP_WAIT1()  asm volatile("cp.async.wait_group 1;" ::: "memory")

static __device__ __forceinline__ uint32_t swz128(uint32_t off) {
    return off ^ ((off >> 3) & 0x70);
}

#define LDSM_X4(r0, r1, r2, r3, addr) \
    asm volatile("ldmatrix.sync.aligned.m8n8.x4.shared.b16 {%0,%1,%2,%3}, [%4];" \
        : "=r"(r0), "=r"(r1), "=r"(r2), "=r"(r3) : "r"(addr))

static __device__ __forceinline__ void mma16816(
    float* d, const uint32_t* a, uint32_t b0, uint32_t b1)
{
    asm volatile(
        "mma.sync.aligned.m16n8k16.row.col.f32.bf16.bf16.f32 "
        "{%0,%1,%2,%3}, {%4,%5,%6,%7}, {%8,%9}, {%0,%1,%2,%3};"
        : "+f"(d[0]), "+f"(d[1]), "+f"(d[2]), "+f"(d[3])
        : "r"(a[0]), "r"(a[1]), "r"(a[2]), "r"(a[3]), "r"(b0), "r"(b1));
}

static __device__ __forceinline__ void split2(float x, float y, uint32_t& hh, uint32_t& ll) {
    __nv_bfloat16 hx = __float2bfloat16(x);
    __nv_bfloat16 hy = __float2bfloat16(y);
    __nv_bfloat16 lx = __float2bfloat16(x - __bfloat162float(hx));
    __nv_bfloat16 ly = __float2bfloat16(y - __bfloat162float(hy));
    hh = ((uint32_t)__bfloat16_as_ushort(hy) << 16) | __bfloat16_as_ushort(hx);
    ll = ((uint32_t)__bfloat16_as_ushort(ly) << 16) | __bfloat16_as_ushort(lx);
}

// ---------------------------------------------------------------------------
// NT GEMM: out = alpha * A @ B^T (+ bias).
// A: [M,K3] bf16 row-major; B: [N,K3] bf16 row-major. M,N % 128 == 0,
// K3 % 64 == 0, K3/64 >= 2. Batched via blockIdx.z.
// mode 0: fp32 C [M,N].  mode 1: bf16 D [M,3N] slices (hi,hi,lo).
// mode 2: bf16 D [M,3N] slices (hi,lo,hi).
// bias_row != 0: bias indexed by output row instead of column.
// ---------------------------------------------------------------------------
__global__ __launch_bounds__(256, 2)
void gemm_mma_nt(const __nv_bfloat16* __restrict__ A,
                 const __nv_bfloat16* __restrict__ B,
                 const float* __restrict__ bias,
                 float* __restrict__ C,
                 __nv_bfloat16* __restrict__ D,
                 int mode, int bias_row,
                 int M, int N, int K3, float alpha,
                 long long sA, long long sB, long long sOut)
{
    extern __shared__ char dsmem_raw[];
    const uint32_t base = smem_u32(dsmem_raw);

    const int tid  = threadIdx.x;
    const int wid  = tid >> 5;
    const int lane = tid & 31;
    const int wm = wid & 3;
    const int wn = wid >> 2;
    const long long z = blockIdx.z;
    const int row0 = blockIdx.y * 128;
    const int col0 = blockIdx.x * 128;

    const __nv_bfloat16* Ab = A + z * sA + (long long)row0 * K3;
    const __nv_bfloat16* Bb = B + z * sB + (long long)col0 * K3;

    const int KI = K3 >> 6;

    const int ldr0 = tid >> 3;
    const int ldc  = tid & 7;

    const int g = lane >> 3;
    const int arow = wm * 32 + (g & 1) * 8 + (lane & 7);
    const int ach  = g >> 1;
    const int brow = wn * 64 + (g >> 1) * 8 + (lane & 7);
    const int bch  = g & 1;

    float acc[2][8][4];
#pragma unroll
    for (int t = 0; t < 2; ++t)
#pragma unroll
        for (int u = 0; u < 8; ++u)
#pragma unroll
            for (int r = 0; r < 4; ++r) acc[t][u][r] = 0.0f;

    auto load_stage = [&](int kb) {
        const uint32_t sa = base + (kb % NSTG) * STG_BYTES;
        const uint32_t sb = base + NSTG * STG_BYTES + (kb % NSTG) * STG_BYTES;
        const long long k0 = (long long)kb * 64 + ldc * 8;
#pragma unroll
        for (int i = 0; i < 4; ++i) {
            const int r = ldr0 + i * 32;
            const uint32_t so = swz128((uint32_t)(r * 128 + ldc * 16));
            cp_async16(sa + so, Ab + (long long)r * K3 + k0);
            cp_async16(sb + so, Bb + (long long)r * K3 + k0);
        }
    };

    load_stage(0); CP_COMMIT();
    load_stage(1); CP_COMMIT();

    for (int it = 0; it < KI; ++it) {
        CP_WAIT1();                  // stage `it` resident (<=1 group pending)
        __syncthreads();             // all warps done reading stage it-1

        // prefetch stage it+2 (reuses buffer of stage it-1 — safe post-sync)
        if (it + 2 < KI) load_stage(it + 2);
        CP_COMMIT();

        const int s = it % NSTG;
        const uint32_t sa = base + s * STG_BYTES;
        const uint32_t sb = base + NSTG * STG_BYTES + s * STG_BYTES;

#pragma unroll
        for (int kk = 0; kk < 4; ++kk) {
            uint32_t af[2][4];
#pragma unroll
            for (int t = 0; t < 2; ++t) {
                const uint32_t ad = sa + swz128(
                    (uint32_t)((arow + t * 16) * 128 + (kk * 2 + ach) * 16));
                LDSM_X4(af[t][0], af[t][1], af[t][2], af[t][3], ad);
            }
            uint32_t bf[4][4];
#pragma unroll
            for (int p = 0; p < 4; ++p) {
                const uint32_t bd = sb + swz128(
                    (uint32_t)((brow + p * 16) * 128 + (kk * 2 + bch) * 16));
                LDSM_X4(bf[p][0], bf[p][1], bf[p][2], bf[p][3], bd);
            }
#pragma unroll
            for (int t = 0; t < 2; ++t)
#pragma unroll
                for (int u = 0; u < 8; ++u)
                    mma16816(acc[t][u], af[t],
                             bf[u >> 1][(u & 1) * 2], bf[u >> 1][(u & 1) * 2 + 1]);
        }
    }

    // ---- epilogue ----
    if (mode == 0) {
        float* Cz = C + z * sOut;
#pragma unroll
        for (int t = 0; t < 2; ++t) {
            const int r_lo = row0 + wm * 32 + t * 16 + (lane >> 2);
#pragma unroll
            for (int u = 0; u < 8; ++u) {
                const int c = col0 + wn * 64 + u * 8 + 2 * (lane & 3);
                float b0 = 0.f, b1 = 0.f;
                if (bias && !bias_row) { b0 = bias[c]; b1 = bias[c + 1]; }
                const float br0 = (bias && bias_row) ? bias[r_lo] : 0.f;
                const float br1 = (bias && bias_row) ? bias[r_lo + 8] : 0.f;
                float2 v0, v1;
                v0.x = acc[t][u][0] * alpha + b0 + br0;
                v0.y = acc[t][u][1] * alpha + b1 + br0;
                v1.x = acc[t][u][2] * alpha + b0 + br1;
                v1.y = acc[t][u][3] * alpha + b1 + br1;
                *(float2*)(Cz + (long long)r_lo * N + c) = v0;
                *(float2*)(Cz + (long long)(r_lo + 8) * N + c) = v1;
            }
        }
    } else {
        __nv_bfloat16* Dz = D + z * sOut;
        const int N3 = 3 * N;
#pragma unroll
        for (int t = 0; t < 2; ++t) {
            const int r_lo = row0 + wm * 32 + t * 16 + (lane >> 2);
#pragma unroll
            for (int u = 0; u < 8; ++u) {
                const int c = col0 + wn * 64 + u * 8 + 2 * (lane & 3);
                float b0 = 0.f, b1 = 0.f;
                if (bias && !bias_row) { b0 = bias[c]; b1 = bias[c + 1]; }
#pragma unroll
                for (int half = 0; half < 2; ++half) {
                    const int r = r_lo + half * 8;
                    const float br = (bias && bias_row) ? bias[r] : 0.f;
                    const float vx = acc[t][u][half * 2 + 0] * alpha + b0 + br;
                    const float vy = acc[t][u][half * 2 + 1] * alpha + b1 + br;
                    uint32_t hh, ll;
                    split2(vx, vy, hh, ll);
                    *(uint32_t*)(Dz + (long long)r * N3 + c)         = hh;
                    *(uint32_t*)(Dz + (long long)r * N3 + N + c)     = (mode == 1) ? hh : ll;
                    *(uint32_t*)(Dz + (long long)r * N3 + 2 * N + c) = (mode == 1) ? ll : hh;
                }
            }
        }
    }
}

// ---------------------------------------------------------------------------
// fp32 [R,K] -> bf16 [R,3K] split, 8 elems/thread, pattern A (hi,hi,lo).
// z=0: src0->dst0, z=1: src1->dst1.
// ---------------------------------------------------------------------------
__global__ __launch_bounds__(256) void conv_split8_2(
    const float* __restrict__ src0, __nv_bfloat16* __restrict__ dst0,
    const float* __restrict__ src1, __nv_bfloat16* __restrict__ dst1,
    int K, long long total8)
{
    const long long i = (long long)blockIdx.x * 256 + threadIdx.x;
    if (i >= total8) return;
    const float* src = blockIdx.z ? src1 : src0;
    __nv_bfloat16* dst = blockIdx.z ? dst1 : dst0;
    const int K8 = K >> 3;
    const long long row = i / K8;
    const int k0 = (int)(i - row * K8) << 3;

    const float4 va = *(const float4*)(src + row * K + k0);
    const float4 vb = *(const float4*)(src + row * K + k0 + 4);
    float f[8] = {va.x, va.y, va.z, va.w, vb.x, vb.y, vb.z, vb.w};
    uint32_t hh[4], ll[4];
#pragma unroll
    for (int j = 0; j < 4; ++j) split2(f[2 * j], f[2 * j + 1], hh[j], ll[j]);

    uint4 H = make_uint4(hh[0], hh[1], hh[2], hh[3]);
    uint4 L = make_uint4(ll[0], ll[1], ll[2], ll[3]);
    __nv_bfloat16* d0 = dst + row * 3LL * K + k0;
    *(uint4*)(d0)         = H;
    *(uint4*)(d0 + K)     = H;
    *(uint4*)(d0 + 2 * K) = L;
}

// ---------------------------------------------------------------------------
// Weight transpose+split: src fp32 [R,C] -> dst bf16 [C,3R], pattern B.
// Four matrices in one launch (all 768x768).
// ---------------------------------------------------------------------------
__global__ __launch_bounds__(256) void convT_split_w(
    const float* __restrict__ s0, const float* __restrict__ s1,
    const float* __restrict__ s2, const float* __restrict__ s3,
    __nv_bfloat16* __restrict__ d0, __nv_bfloat16* __restrict__ d1,
    __nv_bfloat16* __restrict__ d2, __nv_bfloat16* __restrict__ d3,
    int R, int Csz)
{
    __shared__ float tile[32 * 33];
    const float* Sp = (blockIdx.z == 0) ? s0 : (blockIdx.z == 1) ? s1
                    : (blockIdx.z == 2) ? s2 : s3;
    __nv_bfloat16* Dp = (blockIdx.z == 0) ? d0 : (blockIdx.z == 1) ? d1
                      : (blockIdx.z == 2) ? d2 : d3;
    const int r0 = blockIdx.y * 32;
    const int c0 = blockIdx.x * 32;
    const int tid = threadIdx.x;
    const int tx = tid & 31;
    const int ty = tid >> 5;
#pragma unroll
    for (int j = 0; j < 4; ++j)
        tile[(ty + j * 8) * 33 + tx] = Sp[(long long)(r0 + ty + j * 8) * Csz + c0 + tx];
    __syncthreads();

    const int cl = tid >> 3;
    const int rs = (tid & 7) * 4;
    union { __nv_bfloat16 b[4]; unsigned long long u; } H, L;
#pragma unroll
    for (int j = 0; j < 4; ++j) {
        const float v = tile[(rs + j) * 33 + cl];
        H.b[j] = __float2bfloat16(v);
        L.b[j] = __float2bfloat16(v - __bfloat162float(H.b[j]));
    }
    const long long basee = (long long)(c0 + cl) * 3 * R + (r0 + rs);
    *(unsigned long long*)(Dp + basee)         = H.u;
    *(unsigned long long*)(Dp + basee + R)     = L.u;
    *(unsigned long long*)(Dp + basee + 2 * R) = H.u;
}

// ---------------------------------------------------------------------------
// Fused softmax + split: read fp32 row [1024], write bf16 [3*1024] pattern A.
// ---------------------------------------------------------------------------
__global__ __launch_bounds__(256) void softmax_split(
    const float* __restrict__ s, __nv_bfloat16* __restrict__ dst)
{
    const long long row = blockIdx.x;
    const float* p = s + row * 1024;
    const int tid = threadIdx.x;

    float4 v = *(const float4*)(p + tid * 4);
    __shared__ float red[8];

    float m = fmaxf(fmaxf(v.x, v.y), fmaxf(v.z, v.w));
#pragma unroll
    for (int o = 16; o > 0; o >>= 1) m = fmaxf(m, __shfl_xor_sync(0xffffffffu, m, o));
    if ((tid & 31) == 0) red[tid >> 5] = m;
    __syncthreads();
    float bm = red[0];
#pragma unroll
    for (int i = 1; i < 8; ++i) bm = fmaxf(bm, red[i]);
    __syncthreads();

    v.x = __expf(v.x - bm); v.y = __expf(v.y - bm);
    v.z = __expf(v.z - bm); v.w = __expf(v.w - bm);
    float sum = v.x + v.y + v.z + v.w;
#pragma unroll
    for (int o = 16; o > 0; o >>= 1) sum += __shfl_xor_sync(0xffffffffu, sum, o);
    if ((tid & 31) == 0) red[tid >> 5] = sum;
    __syncthreads();
    float bs = red[0];
#pragma unroll
    for (int i = 1; i < 8; ++i) bs += red[i];

    const float inv = 1.0f / bs;
    v.x *= inv; v.y *= inv; v.z *= inv; v.w *= inv;

    uint32_t h0, l0, h1, l1;
    split2(v.x, v.y, h0, l0);
    split2(v.z, v.w, h1, l1);
    uint2 H = make_uint2(h0, h1);
    uint2 L = make_uint2(l0, l1);
    __nv_bfloat16* d0 = dst + row * 3072 + tid * 4;
    *(uint2*)(d0)        = H;
    *(uint2*)(d0 + 1024) = H;
    *(uint2*)(d0 + 2048) = L;
}

// ---------------------------------------------------------------------------
extern "C" void kernel_launch(void* const* d_in, const int* in_sizes, int n_in,
                              void* d_out, int out_size)
{
    const float* x   = (const float*)d_in[0];
    const float* enc = (const float*)d_in[1];
    const float* Wq  = (const float*)d_in[2];
    const float* bq  = (const float*)d_in[3];
    const float* Wk  = (const float*)d_in[4];
    const float* bk  = (const float*)d_in[5];
    const float* Wv  = (const float*)d_in[6];
    const float* bv  = (const float*)d_in[7];
    const float* Wp  = (const float*)d_in[8];
    const float* bp  = (const float*)d_in[9];
    float* out = (float*)d_out;

    float* scores;
    __nv_bfloat16 *xc, *encc, *qc, *kc, *vtc, *attnc, *wqt, *wkt, *wvt, *wpt;
    cudaGetSymbolAddress((void**)&scores, g_scores);
    cudaGetSymbolAddress((void**)&xc, g_xc);
    cudaGetSymbolAddress((void**)&encc, g_encc);
    cudaGetSymbolAddress((void**)&qc, g_qc);
    cudaGetSymbolAddress((void**)&kc, g_kc);
    cudaGetSymbolAddress((void**)&vtc, g_vtc);
    cudaGetSymbolAddress((void**)&attnc, g_attnc);
    cudaGetSymbolAddress((void**)&wqt, g_wqt);
    cudaGetSymbolAddress((void**)&wkt, g_wkt);
    cudaGetSymbolAddress((void**)&wvt, g_wvt);
    cudaGetSymbolAddress((void**)&wpt, g_wpt);

    cudaFuncSetAttribute(gemm_mma_nt,
                         cudaFuncAttributeMaxDynamicSharedMemorySize, DSMEM_BYTES);

    const int BT = Bb_ * T_;                 // 8192
    const float scale = 1.0f / sqrtf((float)Hh_);
    dim3 blk(256);

    // 1. Weight transposes+splits (pattern B), one launch
    {
        dim3 g(E_ / 32, E_ / 32, 4);
        convT_split_w<<<g, blk>>>(Wq, Wk, Wv, Wp, wqt, wkt, wvt, wpt, E_, Hh_);
    }

    // 2. x & enc splits (pattern A), one launch
    {
        long long t8 = (long long)BT * E_ / 8;
        dim3 g((unsigned)((t8 + 255) / 256), 1, 2);
        conv_split8_2<<<g, blk>>>(x, xc, enc, encc, E_, t8);
    }

    // 3. Q, K projections (split epilogues); V^T directly by GEMM (row bias)
    {
        dim3 g(Hh_ / 128, BT / 128, 1);
        gemm_mma_nt<<<g, blk, DSMEM_BYTES>>>(xc,   wqt, bq, nullptr, qc, 1, 0,
                                             BT, Hh_, 3 * E_, 1.0f, 0, 0, 0);
        gemm_mma_nt<<<g, blk, DSMEM_BYTES>>>(encc, wkt, bk, nullptr, kc, 2, 0,
                                             BT, Hh_, 3 * E_, 1.0f, 0, 0, 0);
        // v^T[b]: [Hh, S] = wvt(Hh,3E) x encc[b](S,3E); pattern B split -> vtc
        dim3 gv(S_ / 128, Hh_ / 128, Bb_);
        gemm_mma_nt<<<gv, blk, DSMEM_BYTES>>>(wvt, encc, bv, nullptr, vtc, 2, 1,
                                              Hh_, S_, 3 * E_, 1.0f,
                                              0, (long long)S_ * 3 * E_,
                                              (long long)Hh_ * 3 * S_);
    }

    // 4. scores[b] = q[b] k[b]^T * scale  (fp32)
    {
        dim3 g(S_ / 128, T_ / 128, Bb_);
        gemm_mma_nt<<<g, blk, DSMEM_BYTES>>>(qc, kc, nullptr, scores, nullptr, 0, 0,
                                             T_, S_, 3 * Hh_, scale,
                                             (long long)T_ * 3 * Hh_,
                                             (long long)S_ * 3 * Hh_,
                                             (long long)T_ * S_);
    }

    // 5. softmax + split (pattern A) -> attnc
    softmax_split<<<BT, blk>>>(scores, attnc);

    // 6. attnout[b] = attn[b] @ v[b]; split (pattern A) -> xc
    {
        dim3 g(Hh_ / 128, T_ / 128, Bb_);
        gemm_mma_nt<<<g, blk, DSMEM_BYTES>>>(attnc, vtc, nullptr, nullptr, xc, 1, 0,
                                             T_, Hh_, 3 * S_, 1.0f,
                                             (long long)T_ * 3 * S_,
                                             (long long)Hh_ * 3 * S_,
                                             (long long)T_ * 3 * Hh_);
    }

    // 7. out = attnout @ Wp + bp  (fp32)
    {
        dim3 g(E_ / 128, BT / 128, 1);
        gemm_mma_nt<<<g, blk, DSMEM_BYTES>>>(xc, wpt, bp, out, nullptr, 0, 0,
                                             BT, E_, 3 * Hh_, 1.0f, 0, 0, 0);
    }
}

// round 8
// speedup vs baseline: 2.5495x; 1.0191x over previous
#include <cuda_runtime.h>
#include <cuda_bf16.h>
#include <math.h>
#include <stdint.h>

// ============================================================================
// CrossAttention via bf16 mma.sync + 3-term error compensation.
//   C = A*B^T ~= A_hi*B_hi + A_hi*B_lo + A_lo*B_hi   (K -> 3K concat)
// NT GEMMs, 128x128 tile, BK=64 (SW128 rows), 3-stage cp.async, one sync/iter,
// register double-buffered ldmatrix fragments. Splits fused into epilogues.
// ============================================================================

static const int Bb_ = 8, T_ = 1024, S_ = 1024, E_ = 768, Hh_ = 768;

#define STG_BYTES 16384           // 128 rows x 128B
#define NSTG 3
#define DSMEM_BYTES (NSTG * 2 * STG_BYTES)

// scratch
__device__ float g_scores[8 * 1024 * 1024];
__device__ __nv_bfloat16 g_xc[8192LL * 2304];     // x split; later attnout split
__device__ __nv_bfloat16 g_encc[8192LL * 2304];
__device__ __nv_bfloat16 g_qc[8192LL * 2304];
__device__ __nv_bfloat16 g_kc[8192LL * 2304];
__device__ __nv_bfloat16 g_vtc[8LL * 768 * 3072];
__device__ __nv_bfloat16 g_attnc[8192LL * 3072];
__device__ __nv_bfloat16 g_wqt[768LL * 2304];
__device__ __nv_bfloat16 g_wkt[768LL * 2304];
__device__ __nv_bfloat16 g_wvt[768LL * 2304];
__device__ __nv_bfloat16 g_wpt[768LL * 2304];

// ---------------------------------------------------------------------------
static __device__ __forceinline__ uint32_t smem_u32(const void* p) {
    return (uint32_t)__cvta_generic_to_shared((void*)p);
}
static __device__ __forceinline__ void cp_async16(uint32_t dst, const void* src) {
    asm volatile("cp.async.cg.shared.global [%0], [%1], 16;" :: "r"(dst), "l"(src) : "memory");
}
#define CP_COMMIT() asm volatile("cp.async.commit_group;" ::: "memory")
#define CP_WAIT1()  asm volatile("cp.async.wait_group 1;" ::: "memory")

static __device__ __forceinline__ uint32_t swz128(uint32_t off) {
    return off ^ ((off >> 3) & 0x70);
}

#define LDSM_X4(r0, r1, r2, r3, addr) \
    asm volatile("ldmatrix.sync.aligned.m8n8.x4.shared.b16 {%0,%1,%2,%3}, [%4];" \
        : "=r"(r0), "=r"(r1), "=r"(r2), "=r"(r3) : "r"(addr))

static __device__ __forceinline__ void mma16816(
    float* d, const uint32_t* a, uint32_t b0, uint32_t b1)
{
    asm volatile(
        "mma.sync.aligned.m16n8k16.row.col.f32.bf16.bf16.f32 "
        "{%0,%1,%2,%3}, {%4,%5,%6,%7}, {%8,%9}, {%0,%1,%2,%3};"
        : "+f"(d[0]), "+f"(d[1]), "+f"(d[2]), "+f"(d[3])
        : "r"(a[0]), "r"(a[1]), "r"(a[2]), "r"(a[3]), "r"(b0), "r"(b1));
}

static __device__ __forceinline__ void split2(float x, float y, uint32_t& hh, uint32_t& ll) {
    __nv_bfloat16 hx = __float2bfloat16(x);
    __nv_bfloat16 hy = __float2bfloat16(y);
    __nv_bfloat16 lx = __float2bfloat16(x - __bfloat162float(hx));
    __nv_bfloat16 ly = __float2bfloat16(y - __bfloat162float(hy));
    hh = ((uint32_t)__bfloat16_as_ushort(hy) << 16) | __bfloat16_as_ushort(hx);
    ll = ((uint32_t)__bfloat16_as_ushort(ly) << 16) | __bfloat16_as_ushort(lx);
}

// ---------------------------------------------------------------------------
// NT GEMM: out = alpha * A @ B^T (+ bias).
// A: [M,K3] bf16 row-major; B: [N,K3] bf16 row-major. M,N % 128 == 0,
// K3 % 64 == 0. Batched via blockIdx.z.
// mode 0: fp32 C [M,N]. mode 1: bf16 D [M,3N] (hi,hi,lo). mode 2: (hi,lo,hi).
// bias_row != 0: bias indexed by output row.
// z_qk != 0: blockIdx.z==1 selects {A2,B2,bias2,D2, mode 2}.
// ---------------------------------------------------------------------------
__global__ __launch_bounds__(256, 2)
void gemm_mma_nt(const __nv_bfloat16* __restrict__ A,
                 const __nv_bfloat16* __restrict__ B,
                 const float* __restrict__ bias,
                 float* __restrict__ C,
                 __nv_bfloat16* __restrict__ D,
                 int mode, int bias_row, int z_qk,
                 const __nv_bfloat16* __restrict__ A2,
                 const __nv_bfloat16* __restrict__ B2,
                 const float* __restrict__ bias2,
                 __nv_bfloat16* __restrict__ D2,
                 int M, int N, int K3, float alpha,
                 long long sA, long long sB, long long sOut)
{
    extern __shared__ char dsmem_raw[];
    const uint32_t base = smem_u32(dsmem_raw);

    const int tid  = threadIdx.x;
    const int wid  = tid >> 5;
    const int lane = tid & 31;
    const int wm = wid & 3;
    const int wn = wid >> 2;
    long long z = blockIdx.z;
    if (z_qk) {
        if (z == 1) { A = A2; B = B2; bias = bias2; D = D2; mode = 2; }
        z = 0;
    }
    const int row0 = blockIdx.y * 128;
    const int col0 = blockIdx.x * 128;

    const __nv_bfloat16* Ab = A + z * sA + (long long)row0 * K3;
    const __nv_bfloat16* Bb = B + z * sB + (long long)col0 * K3;

    const int KI = K3 >> 6;

    const int ldr0 = tid >> 3;
    const int ldc  = tid & 7;

    const int g = lane >> 3;
    const int arow = wm * 32 + (g & 1) * 8 + (lane & 7);
    const int ach  = g >> 1;
    const int brow = wn * 64 + (g >> 1) * 8 + (lane & 7);
    const int bch  = g & 1;
    const int a7 = arow & 7;
    const int b7 = brow & 7;
    uint32_t arb[2], brb[4];
#pragma unroll
    for (int t = 0; t < 2; ++t) arb[t] = (uint32_t)(arow + t * 16) * 128u;
#pragma unroll
    for (int p = 0; p < 4; ++p) brb[p] = (uint32_t)(brow + p * 16) * 128u;

    float acc[2][8][4];
#pragma unroll
    for (int t = 0; t < 2; ++t)
#pragma unroll
        for (int u = 0; u < 8; ++u)
#pragma unroll
            for (int r = 0; r < 4; ++r) acc[t][u][r] = 0.0f;

    auto load_stage = [&](int kb) {
        const uint32_t sa = base + (kb % NSTG) * STG_BYTES;
        const uint32_t sb = base + NSTG * STG_BYTES + (kb % NSTG) * STG_BYTES;
        const long long k0 = (long long)kb * 64 + ldc * 8;
#pragma unroll
        for (int i = 0; i < 4; ++i) {
            const int r = ldr0 + i * 32;
            const uint32_t so = swz128((uint32_t)(r * 128 + ldc * 16));
            cp_async16(sa + so, Ab + (long long)r * K3 + k0);
            cp_async16(sb + so, Bb + (long long)r * K3 + k0);
        }
    };

    load_stage(0); CP_COMMIT();
    load_stage(1); CP_COMMIT();

    uint32_t af[2][2][4];    // [buf][t][frag]
    uint32_t bf[2][4][4];    // [buf][p][frag]

    for (int it = 0; it < KI; ++it) {
        CP_WAIT1();
        __syncthreads();

        if (it + 2 < KI) load_stage(it + 2);
        CP_COMMIT();

        const int s = it % NSTG;
        const uint32_t sa = base + s * STG_BYTES;
        const uint32_t sb = base + NSTG * STG_BYTES + s * STG_BYTES;

        // preload kk = 0 fragments
        {
            const uint32_t xa = (uint32_t)((ach ^ a7) * 16);
            const uint32_t xb = (uint32_t)((bch ^ b7) * 16);
#pragma unroll
            for (int t = 0; t < 2; ++t)
                LDSM_X4(af[0][t][0], af[0][t][1], af[0][t][2], af[0][t][3],
                        sa + arb[t] + xa);
#pragma unroll
            for (int p = 0; p < 4; ++p)
                LDSM_X4(bf[0][p][0], bf[0][p][1], bf[0][p][2], bf[0][p][3],
                        sb + brb[p] + xb);
        }

#pragma unroll
        for (int kk = 0; kk < 4; ++kk) {
            const int cur = kk & 1;
            const int nxt = cur ^ 1;
            if (kk < 3) {
                const uint32_t xa = (uint32_t)((((kk + 1) * 2 + ach) ^ a7) * 16);
                const uint32_t xb = (uint32_t)((((kk + 1) * 2 + bch) ^ b7) * 16);
#pragma unroll
                for (int t = 0; t < 2; ++t)
                    LDSM_X4(af[nxt][t][0], af[nxt][t][1], af[nxt][t][2], af[nxt][t][3],
                            sa + arb[t] + xa);
#pragma unroll
                for (int p = 0; p < 4; ++p)
                    LDSM_X4(bf[nxt][p][0], bf[nxt][p][1], bf[nxt][p][2], bf[nxt][p][3],
                            sb + brb[p] + xb);
            }
#pragma unroll
            for (int t = 0; t < 2; ++t)
#pragma unroll
                for (int u = 0; u < 8; ++u)
                    mma16816(acc[t][u], af[cur][t],
                             bf[cur][u >> 1][(u & 1) * 2],
                             bf[cur][u >> 1][(u & 1) * 2 + 1]);
        }
    }

    // ---- epilogue ----
    if (mode == 0) {
        float* Cz = C + z * sOut;
#pragma unroll
        for (int t = 0; t < 2; ++t) {
            const int r_lo = row0 + wm * 32 + t * 16 + (lane >> 2);
#pragma unroll
            for (int u = 0; u < 8; ++u) {
                const int c = col0 + wn * 64 + u * 8 + 2 * (lane & 3);
                float b0 = 0.f, b1 = 0.f;
                if (bias && !bias_row) { b0 = bias[c]; b1 = bias[c + 1]; }
                const float br0 = (bias && bias_row) ? bias[r_lo] : 0.f;
                const float br1 = (bias && bias_row) ? bias[r_lo + 8] : 0.f;
                float2 v0, v1;
                v0.x = acc[t][u][0] * alpha + b0 + br0;
                v0.y = acc[t][u][1] * alpha + b1 + br0;
                v1.x = acc[t][u][2] * alpha + b0 + br1;
                v1.y = acc[t][u][3] * alpha + b1 + br1;
                *(float2*)(Cz + (long long)r_lo * N + c) = v0;
                *(float2*)(Cz + (long long)(r_lo + 8) * N + c) = v1;
            }
        }
    } else {
        __nv_bfloat16* Dz = D + z * sOut;
        const int N3 = 3 * N;
#pragma unroll
        for (int t = 0; t < 2; ++t) {
            const int r_lo = row0 + wm * 32 + t * 16 + (lane >> 2);
#pragma unroll
            for (int u = 0; u < 8; ++u) {
                const int c = col0 + wn * 64 + u * 8 + 2 * (lane & 3);
                float b0 = 0.f, b1 = 0.f;
                if (bias && !bias_row) { b0 = bias[c]; b1 = bias[c + 1]; }
#pragma unroll
                for (int half = 0; half < 2; ++half) {
                    const int r = r_lo + half * 8;
                    const float br = (bias && bias_row) ? bias[r] : 0.f;
                    const float vx = acc[t][u][half * 2 + 0] * alpha + b0 + br;
                    const float vy = acc[t][u][half * 2 + 1] * alpha + b1 + br;
                    uint32_t hh, ll;
                    split2(vx, vy, hh, ll);
                    *(uint32_t*)(Dz + (long long)r * N3 + c)         = hh;
                    *(uint32_t*)(Dz + (long long)r * N3 + N + c)     = (mode == 1) ? hh : ll;
                    *(uint32_t*)(Dz + (long long)r * N3 + 2 * N + c) = (mode == 1) ? ll : hh;
                }
            }
        }
    }
}

// ---------------------------------------------------------------------------
// fp32 [R,K] -> bf16 [R,3K] split, 8 elems/thread, pattern A. z picks src.
// ---------------------------------------------------------------------------
__global__ __launch_bounds__(256) void conv_split8_2(
    const float* __restrict__ src0, __nv_bfloat16* __restrict__ dst0,
    const float* __restrict__ src1, __nv_bfloat16* __restrict__ dst1,
    int K, long long total8)
{
    const long long i = (long long)blockIdx.x * 256 + threadIdx.x;
    if (i >= total8) return;
    const float* src = blockIdx.z ? src1 : src0;
    __nv_bfloat16* dst = blockIdx.z ? dst1 : dst0;
    const int K8 = K >> 3;
    const long long row = i / K8;
    const int k0 = (int)(i - row * K8) << 3;

    const float4 va = *(const float4*)(src + row * K + k0);
    const float4 vb = *(const float4*)(src + row * K + k0 + 4);
    float f[8] = {va.x, va.y, va.z, va.w, vb.x, vb.y, vb.z, vb.w};
    uint32_t hh[4], ll[4];
#pragma unroll
    for (int j = 0; j < 4; ++j) split2(f[2 * j], f[2 * j + 1], hh[j], ll[j]);

    uint4 H = make_uint4(hh[0], hh[1], hh[2], hh[3]);
    uint4 L = make_uint4(ll[0], ll[1], ll[2], ll[3]);
    __nv_bfloat16* d0 = dst + row * 3LL * K + k0;
    *(uint4*)(d0)         = H;
    *(uint4*)(d0 + K)     = H;
    *(uint4*)(d0 + 2 * K) = L;
}

// ---------------------------------------------------------------------------
// Weight transpose+split: fp32 [R,C] -> bf16 [C,3R], pattern B, 4 mats.
// ---------------------------------------------------------------------------
__global__ __launch_bounds__(256) void convT_split_w(
    const float* __restrict__ s0, const float* __restrict__ s1,
    const float* __restrict__ s2, const float* __restrict__ s3,
    __nv_bfloat16* __restrict__ d0, __nv_bfloat16* __restrict__ d1,
    __nv_bfloat16* __restrict__ d2, __nv_bfloat16* __restrict__ d3,
    int R, int Csz)
{
    __shared__ float tile[32 * 33];
    const float* Sp = (blockIdx.z == 0) ? s0 : (blockIdx.z == 1) ? s1
                    : (blockIdx.z == 2) ? s2 : s3;
    __nv_bfloat16* Dp = (blockIdx.z == 0) ? d0 : (blockIdx.z == 1) ? d1
                      : (blockIdx.z == 2) ? d2 : d3;
    const int r0 = blockIdx.y * 32;
    const int c0 = blockIdx.x * 32;
    const int tid = threadIdx.x;
    const int tx = tid & 31;
    const int ty = tid >> 5;
#pragma unroll
    for (int j = 0; j < 4; ++j)
        tile[(ty + j * 8) * 33 + tx] = Sp[(long long)(r0 + ty + j * 8) * Csz + c0 + tx];
    __syncthreads();

    const int cl = tid >> 3;
    const int rs = (tid & 7) * 4;
    union { __nv_bfloat16 b[4]; unsigned long long u; } H, L;
#pragma unroll
    for (int j = 0; j < 4; ++j) {
        const float v = tile[(rs + j) * 33 + cl];
        H.b[j] = __float2bfloat16(v);
        L.b[j] = __float2bfloat16(v - __bfloat162float(H.b[j]));
    }
    const long long basee = (long long)(c0 + cl) * 3 * R + (r0 + rs);
    *(unsigned long long*)(Dp + basee)         = H.u;
    *(unsigned long long*)(Dp + basee + R)     = L.u;
    *(unsigned long long*)(Dp + basee + 2 * R) = H.u;
}

// ---------------------------------------------------------------------------
// Fused softmax + split: fp32 row [1024] -> bf16 [3*1024] pattern A.
// ---------------------------------------------------------------------------
__global__ __launch_bounds__(256) void softmax_split(
    const float* __restrict__ s, __nv_bfloat16* __restrict__ dst)
{
    const long long row = blockIdx.x;
    const float* p = s + row * 1024;
    const int tid = threadIdx.x;

    float4 v = *(const float4*)(p + tid * 4);
    __shared__ float red[8];

    float m = fmaxf(fmaxf(v.x, v.y), fmaxf(v.z, v.w));
#pragma unroll
    for (int o = 16; o > 0; o >>= 1) m = fmaxf(m, __shfl_xor_sync(0xffffffffu, m, o));
    if ((tid & 31) == 0) red[tid >> 5] = m;
    __syncthreads();
    float bm = red[0];
#pragma unroll
    for (int i = 1; i < 8; ++i) bm = fmaxf(bm, red[i]);
    __syncthreads();

    v.x = __expf(v.x - bm); v.y = __expf(v.y - bm);
    v.z = __expf(v.z - bm); v.w = __expf(v.w - bm);
    float sum = v.x + v.y + v.z + v.w;
#pragma unroll
    for (int o = 16; o > 0; o >>= 1) sum += __shfl_xor_sync(0xffffffffu, sum, o);
    if ((tid & 31) == 0) red[tid >> 5] = sum;
    __syncthreads();
    float bs = red[0];
#pragma unroll
    for (int i = 1; i < 8; ++i) bs += red[i];

    const float inv = 1.0f / bs;
    v.x *= inv; v.y *= inv; v.z *= inv; v.w *= inv;

    uint32_t h0, l0, h1, l1;
    split2(v.x, v.y, h0, l0);
    split2(v.z, v.w, h1, l1);
    uint2 H = make_uint2(h0, h1);
    uint2 L = make_uint2(l0, l1);
    __nv_bfloat16* d0 = dst + row * 3072 + tid * 4;
    *(uint2*)(d0)        = H;
    *(uint2*)(d0 + 1024) = H;
    *(uint2*)(d0 + 2048) = L;
}

// ---------------------------------------------------------------------------
extern "C" void kernel_launch(void* const* d_in, const int* in_sizes, int n_in,
                              void* d_out, int out_size)
{
    const float* x   = (const float*)d_in[0];
    const float* enc = (const float*)d_in[1];
    const float* Wq  = (const float*)d_in[2];
    const float* bq  = (const float*)d_in[3];
    const float* Wk  = (const float*)d_in[4];
    const float* bk  = (const float*)d_in[5];
    const float* Wv  = (const float*)d_in[6];
    const float* bv  = (const float*)d_in[7];
    const float* Wp  = (const float*)d_in[8];
    const float* bp  = (const float*)d_in[9];
    float* out = (float*)d_out;

    float* scores;
    __nv_bfloat16 *xc, *encc, *qc, *kc, *vtc, *attnc, *wqt, *wkt, *wvt, *wpt;
    cudaGetSymbolAddress((void**)&scores, g_scores);
    cudaGetSymbolAddress((void**)&xc, g_xc);
    cudaGetSymbolAddress((void**)&encc, g_encc);
    cudaGetSymbolAddress((void**)&qc, g_qc);
    cudaGetSymbolAddress((void**)&kc, g_kc);
    cudaGetSymbolAddress((void**)&vtc, g_vtc);
    cudaGetSymbolAddress((void**)&attnc, g_attnc);
    cudaGetSymbolAddress((void**)&wqt, g_wqt);
    cudaGetSymbolAddress((void**)&wkt, g_wkt);
    cudaGetSymbolAddress((void**)&wvt, g_wvt);
    cudaGetSymbolAddress((void**)&wpt, g_wpt);

    cudaFuncSetAttribute(gemm_mma_nt,
                         cudaFuncAttributeMaxDynamicSharedMemorySize, DSMEM_BYTES);

    const int BT = Bb_ * T_;                 // 8192
    const float scale = 1.0f / sqrtf((float)Hh_);
    dim3 blk(256);

    // 1. Weight transposes+splits (pattern B), one launch
    {
        dim3 g(E_ / 32, E_ / 32, 4);
        convT_split_w<<<g, blk>>>(Wq, Wk, Wv, Wp, wqt, wkt, wvt, wpt, E_, Hh_);
    }

    // 2. x & enc splits (pattern A), one launch
    {
        long long t8 = (long long)BT * E_ / 8;
        dim3 g((unsigned)((t8 + 255) / 256), 1, 2);
        conv_split8_2<<<g, blk>>>(x, xc, enc, encc, E_, t8);
    }

    // 3. Q+K projections merged (z selects, B2=wkt); V^T by GEMM (row bias)
    {
        dim3 gqk(Hh_ / 128, BT / 128, 2);
        gemm_mma_nt<<<gqk, blk, DSMEM_BYTES>>>(xc, wqt, bq, nullptr, qc, 1, 0, 1,
                                               encc, wkt, bk, kc,
                                               BT, Hh_, 3 * E_, 1.0f, 0, 0, 0);
        dim3 gv(S_ / 128, Hh_ / 128, Bb_);
        gemm_mma_nt<<<gv, blk, DSMEM_BYTES>>>(wvt, encc, bv, nullptr, vtc, 2, 1, 0,
                                              nullptr, nullptr, nullptr, nullptr,
                                              Hh_, S_, 3 * E_, 1.0f,
                                              0, (long long)S_ * 3 * E_,
                                              (long long)Hh_ * 3 * S_);
    }

    // 4. scores[b] = q[b] k[b]^T * scale  (fp32)
    {
        dim3 g(S_ / 128, T_ / 128, Bb_);
        gemm_mma_nt<<<g, blk, DSMEM_BYTES>>>(qc, kc, nullptr, scores, nullptr, 0, 0, 0,
                                             nullptr, nullptr, nullptr, nullptr,
                                             T_, S_, 3 * Hh_, scale,
                                             (long long)T_ * 3 * Hh_,
                                             (long long)S_ * 3 * Hh_,
                                             (long long)T_ * S_);
    }

    // 5. softmax + split (pattern A) -> attnc
    softmax_split<<<BT, blk>>>(scores, attnc);

    // 6. attnout[b] = attn[b] @ v[b]; split (pattern A) -> xc
    {
        dim3 g(Hh_ / 128, T_ / 128, Bb_);
        gemm_mma_nt<<<g, blk, DSMEM_BYTES>>>(attnc, vtc, nullptr, nullptr, xc, 1, 0, 0,
                                             nullptr, nullptr, nullptr, nullptr,
                                             T_, Hh_, 3 * S_, 1.0f,
                                             (long long)T_ * 3 * S_,
                                             (long long)Hh_ * 3 * S_,
                                             (long long)T_ * 3 * Hh_);
    }

    // 7. out = attnout @ Wp + bp  (fp32)
    {
        dim3 g(E_ / 128, BT / 128, 1);
        gemm_mma_nt<<<g, blk, DSMEM_BYTES>>>(xc, wpt, bp, out, nullptr, 0, 0, 0,
                                             nullptr, nullptr, nullptr, nullptr,
                                             BT, E_, 3 * Hh_, 1.0f, 0, 0, 0);
    }
}

// round 10
// speedup vs baseline: 3.6974x; 1.4502x over previous
#include <cuda_runtime.h>
#include <cuda_fp16.h>
#include <math.h>
#include <stdint.h>

// ============================================================================
// CrossAttention via fp16 mma.sync + 2-slice error compensation.
//   C = A*B ~= (A_hi + A_lo) * B_hi     (K -> 2K concat; [h,l] x [h,h])
// fp16 hi/lo gives ~22-bit effective mantissa on the split side; residual is
// the [h,h]-side rounding (~2^-11). NT GEMMs, 128x128 tile, BK=64 (SW128
// rows), 3-stage cp.async, one sync/iter, register double-buffered ldmatrix.
// ============================================================================

static const int Bb_ = 8, T_ = 1024, S_ = 1024, E_ = 768, Hh_ = 768;

#define STG_BYTES 16384           // 128 rows x 128B
#define NSTG 3
#define DSMEM_BYTES (NSTG * 2 * STG_BYTES)

// scratch (sized generously; fp16 2-slice needs less than bf16 3-slice did)
__device__ float g_scores[8 * 1024 * 1024];
__device__ __half g_xc[8192LL * 1536];      // x split; later attnout split
__device__ __half g_encc[8192LL * 1536];
__device__ __half g_qc[8192LL * 1536];
__device__ __half g_kc[8192LL * 1536];
__device__ __half g_vtc[8LL * 768 * 2048];
__device__ __half g_attnc[8192LL * 2048];
__device__ __half g_wqt[768LL * 1536];
__device__ __half g_wkt[768LL * 1536];
__device__ __half g_wvt[768LL * 1536];
__device__ __half g_wpt[768LL * 1536];

// ---------------------------------------------------------------------------
static __device__ __forceinline__ uint32_t smem_u32(const void* p) {
    return (uint32_t)__cvta_generic_to_shared((void*)p);
}
static __device__ __forceinline__ void cp_async16(uint32_t dst, const void* src) {
    asm volatile("cp.async.cg.shared.global [%0], [%1], 16;" :: "r"(dst), "l"(src) : "memory");
}
#define CP_COMMIT() asm volatile("cp.async.commit_group;" ::: "memory")
#define CP_WAIT1()  asm volatile("cp.async.wait_group 1;" ::: "memory")

static __device__ __forceinline__ uint32_t swz128(uint32_t off) {
    return off ^ ((off >> 3) & 0x70);
}

#define LDSM_X4(r0, r1, r2, r3, addr) \
    asm volatile("ldmatrix.sync.aligned.m8n8.x4.shared.b16 {%0,%1,%2,%3}, [%4];" \
        : "=r"(r0), "=r"(r1), "=r"(r2), "=r"(r3) : "r"(addr))

static __device__ __forceinline__ void mma16816(
    float* d, const uint32_t* a, uint32_t b0, uint32_t b1)
{
    asm volatile(
        "mma.sync.aligned.m16n8k16.row.col.f32.f16.f16.f32 "
        "{%0,%1,%2,%3}, {%4,%5,%6,%7}, {%8,%9}, {%0,%1,%2,%3};"
        : "+f"(d[0]), "+f"(d[1]), "+f"(d[2]), "+f"(d[3])
        : "r"(a[0]), "r"(a[1]), "r"(a[2]), "r"(a[3]), "r"(b0), "r"(b1));
}

// pack two fp32 into fp16x2 hi-parts and lo-parts
static __device__ __forceinline__ void split2(float x, float y, uint32_t& hh, uint32_t& ll) {
    __half hx = __float2half(x);
    __half hy = __float2half(y);
    __half lx = __float2half(x - __half2float(hx));
    __half ly = __float2half(y - __half2float(hy));
    hh = ((uint32_t)__half_as_ushort(hy) << 16) | __half_as_ushort(hx);
    ll = ((uint32_t)__half_as_ushort(ly) << 16) | __half_as_ushort(lx);
}

// ---------------------------------------------------------------------------
// NT GEMM: out = alpha * A @ B^T (+ bias).
// A: [M,K2] fp16 row-major; B: [N,K2] fp16 row-major. M,N % 128 == 0,
// K2 % 64 == 0, K2/64 >= 2. Batched via blockIdx.z.
// mode 0: fp32 C [M,N]. mode 1: fp16 D [M,2N] slices (hi,lo).
// mode 2: fp16 D [M,2N] slices (hi,hi).
// bias_row != 0: bias indexed by output row.
// z_qk != 0: blockIdx.z==1 selects {A2,B2,bias2,D2, mode 2}.
// ---------------------------------------------------------------------------
__global__ __launch_bounds__(256, 2)
void gemm_mma_nt(const __half* __restrict__ A,
                 const __half* __restrict__ B,
                 const float* __restrict__ bias,
                 float* __restrict__ C,
                 __half* __restrict__ D,
                 int mode, int bias_row, int z_qk,
                 const __half* __restrict__ A2,
                 const __half* __restrict__ B2,
                 const float* __restrict__ bias2,
                 __half* __restrict__ D2,
                 int M, int N, int K2, float alpha,
                 long long sA, long long sB, long long sOut)
{
    extern __shared__ char dsmem_raw[];
    const uint32_t base = smem_u32(dsmem_raw);

    const int tid  = threadIdx.x;
    const int wid  = tid >> 5;
    const int lane = tid & 31;
    const int wm = wid & 3;
    const int wn = wid >> 2;
    long long z = blockIdx.z;
    if (z_qk) {
        if (z == 1) { A = A2; B = B2; bias = bias2; D = D2; mode = 2; }
        z = 0;
    }
    const int row0 = blockIdx.y * 128;
    const int col0 = blockIdx.x * 128;

    const __half* Ab = A + z * sA + (long long)row0 * K2;
    const __half* Bb = B + z * sB + (long long)col0 * K2;

    const int KI = K2 >> 6;

    const int ldr0 = tid >> 3;
    const int ldc  = tid & 7;

    const int g = lane >> 3;
    const int arow = wm * 32 + (g & 1) * 8 + (lane & 7);
    const int ach  = g >> 1;
    const int brow = wn * 64 + (g >> 1) * 8 + (lane & 7);
    const int bch  = g & 1;
    const int a7 = arow & 7;
    const int b7 = brow & 7;
    uint32_t arb[2], brb[4];
#pragma unroll
    for (int t = 0; t < 2; ++t) arb[t] = (uint32_t)(arow + t * 16) * 128u;
#pragma unroll
    for (int p = 0; p < 4; ++p) brb[p] = (uint32_t)(brow + p * 16) * 128u;

    float acc[2][8][4];
#pragma unroll
    for (int t = 0; t < 2; ++t)
#pragma unroll
        for (int u = 0; u < 8; ++u)
#pragma unroll
            for (int r = 0; r < 4; ++r) acc[t][u][r] = 0.0f;

    auto load_stage = [&](int kb) {
        const uint32_t sa = base + (kb % NSTG) * STG_BYTES;
        const uint32_t sb = base + NSTG * STG_BYTES + (kb % NSTG) * STG_BYTES;
        const long long k0 = (long long)kb * 64 + ldc * 8;
#pragma unroll
        for (int i = 0; i < 4; ++i) {
            const int r = ldr0 + i * 32;
            const uint32_t so = swz128((uint32_t)(r * 128 + ldc * 16));
            cp_async16(sa + so, Ab + (long long)r * K2 + k0);
            cp_async16(sb + so, Bb + (long long)r * K2 + k0);
        }
    };

    load_stage(0); CP_COMMIT();
    load_stage(1); CP_COMMIT();

    uint32_t af[2][2][4];    // [buf][t][frag]
    uint32_t bf[2][4][4];    // [buf][p][frag]

    for (int it = 0; it < KI; ++it) {
        CP_WAIT1();
        __syncthreads();

        if (it + 2 < KI) load_stage(it + 2);
        CP_COMMIT();

        const int s = it % NSTG;
        const uint32_t sa = base + s * STG_BYTES;
        const uint32_t sb = base + NSTG * STG_BYTES + s * STG_BYTES;

        // preload kk = 0 fragments
        {
            const uint32_t xa = (uint32_t)((ach ^ a7) * 16);
            const uint32_t xb = (uint32_t)((bch ^ b7) * 16);
#pragma unroll
            for (int t = 0; t < 2; ++t)
                LDSM_X4(af[0][t][0], af[0][t][1], af[0][t][2], af[0][t][3],
                        sa + arb[t] + xa);
#pragma unroll
            for (int p = 0; p < 4; ++p)
                LDSM_X4(bf[0][p][0], bf[0][p][1], bf[0][p][2], bf[0][p][3],
                        sb + brb[p] + xb);
        }

#pragma unroll
        for (int kk = 0; kk < 4; ++kk) {
            const int cur = kk & 1;
            const int nxt = cur ^ 1;
            if (kk < 3) {
                const uint32_t xa = (uint32_t)((((kk + 1) * 2 + ach) ^ a7) * 16);
                const uint32_t xb = (uint32_t)((((kk + 1) * 2 + bch) ^ b7) * 16);
#pragma unroll
                for (int t = 0; t < 2; ++t)
                    LDSM_X4(af[nxt][t][0], af[nxt][t][1], af[nxt][t][2], af[nxt][t][3],
                            sa + arb[t] + xa);
#pragma unroll
                for (int p = 0; p < 4; ++p)
                    LDSM_X4(bf[nxt][p][0], bf[nxt][p][1], bf[nxt][p][2], bf[nxt][p][3],
                            sb + brb[p] + xb);
            }
#pragma unroll
            for (int t = 0; t < 2; ++t)
#pragma unroll
                for (int u = 0; u < 8; ++u)
                    mma16816(acc[t][u], af[cur][t],
                             bf[cur][u >> 1][(u & 1) * 2],
                             bf[cur][u >> 1][(u & 1) * 2 + 1]);
        }
    }

    // ---- epilogue ----
    if (mode == 0) {
        float* Cz = C + z * sOut;
#pragma unroll
        for (int t = 0; t < 2; ++t) {
            const int r_lo = row0 + wm * 32 + t * 16 + (lane >> 2);
#pragma unroll
            for (int u = 0; u < 8; ++u) {
                const int c = col0 + wn * 64 + u * 8 + 2 * (lane & 3);
                float b0 = 0.f, b1 = 0.f;
                if (bias && !bias_row) { b0 = bias[c]; b1 = bias[c + 1]; }
                const float br0 = (bias && bias_row) ? bias[r_lo] : 0.f;
                const float br1 = (bias && bias_row) ? bias[r_lo + 8] : 0.f;
                float2 v0, v1;
                v0.x = acc[t][u][0] * alpha + b0 + br0;
                v0.y = acc[t][u][1] * alpha + b1 + br0;
                v1.x = acc[t][u][2] * alpha + b0 + br1;
                v1.y = acc[t][u][3] * alpha + b1 + br1;
                *(float2*)(Cz + (long long)r_lo * N + c) = v0;
                *(float2*)(Cz + (long long)(r_lo + 8) * N + c) = v1;
            }
        }
    } else {
        __half* Dz = D + z * sOut;
        const int N2 = 2 * N;
#pragma unroll
        for (int t = 0; t < 2; ++t) {
            const int r_lo = row0 + wm * 32 + t * 16 + (lane >> 2);
#pragma unroll
            for (int u = 0; u < 8; ++u) {
                const int c = col0 + wn * 64 + u * 8 + 2 * (lane & 3);
                float b0 = 0.f, b1 = 0.f;
                if (bias && !bias_row) { b0 = bias[c]; b1 = bias[c + 1]; }
#pragma unroll
                for (int half = 0; half < 2; ++half) {
                    const int r = r_lo + half * 8;
                    const float br = (bias && bias_row) ? bias[r] : 0.f;
                    const float vx = acc[t][u][half * 2 + 0] * alpha + b0 + br;
                    const float vy = acc[t][u][half * 2 + 1] * alpha + b1 + br;
                    uint32_t hh, ll;
                    split2(vx, vy, hh, ll);
                    *(uint32_t*)(Dz + (long long)r * N2 + c)     = hh;
                    *(uint32_t*)(Dz + (long long)r * N2 + N + c) = (mode == 1) ? ll : hh;
                }
            }
        }
    }
}

// ---------------------------------------------------------------------------
// fp32 [R,K] -> fp16 [R,2K] split (hi,lo), 8 elems/thread. z picks src.
// ---------------------------------------------------------------------------
__global__ __launch_bounds__(256) void conv_split8_2(
    const float* __restrict__ src0, __half* __restrict__ dst0,
    const float* __restrict__ src1, __half* __restrict__ dst1,
    int K, long long total8)
{
    const long long i = (long long)blockIdx.x * 256 + threadIdx.x;
    if (i >= total8) return;
    const float* src = blockIdx.z ? src1 : src0;
    __half* dst = blockIdx.z ? dst1 : dst0;
    const int K8 = K >> 3;
    const long long row = i / K8;
    const int k0 = (int)(i - row * K8) << 3;

    const float4 va = *(const float4*)(src + row * K + k0);
    const float4 vb = *(const float4*)(src + row * K + k0 + 4);
    float f[8] = {va.x, va.y, va.z, va.w, vb.x, vb.y, vb.z, vb.w};
    uint32_t hh[4], ll[4];
#pragma unroll
    for (int j = 0; j < 4; ++j) split2(f[2 * j], f[2 * j + 1], hh[j], ll[j]);

    uint4 H = make_uint4(hh[0], hh[1], hh[2], hh[3]);
    uint4 L = make_uint4(ll[0], ll[1], ll[2], ll[3]);
    __half* d0 = dst + row * 2LL * K + k0;
    *(uint4*)(d0)     = H;
    *(uint4*)(d0 + K) = L;
}

// ---------------------------------------------------------------------------
// Weight transpose+split: fp32 [R,C] -> fp16 [C,2R] (hi,hi), 4 mats.
// ---------------------------------------------------------------------------
__global__ __launch_bounds__(256) void convT_split_w(
    const float* __restrict__ s0, const float* __restrict__ s1,
    const float* __restrict__ s2, const float* __restrict__ s3,
    __half* __restrict__ d0, __half* __restrict__ d1,
    __half* __restrict__ d2, __half* __restrict__ d3,
    int R, int Csz)
{
    __shared__ float tile[32 * 33];
    const float* Sp = (blockIdx.z == 0) ? s0 : (blockIdx.z == 1) ? s1
                    : (blockIdx.z == 2) ? s2 : s3;
    __half* Dp = (blockIdx.z == 0) ? d0 : (blockIdx.z == 1) ? d1
               : (blockIdx.z == 2) ? d2 : d3;
    const int r0 = blockIdx.y * 32;
    const int c0 = blockIdx.x * 32;
    const int tid = threadIdx.x;
    const int tx = tid & 31;
    const int ty = tid >> 5;
#pragma unroll
    for (int j = 0; j < 4; ++j)
        tile[(ty + j * 8) * 33 + tx] = Sp[(long long)(r0 + ty + j * 8) * Csz + c0 + tx];
    __syncthreads();

    const int cl = tid >> 3;
    const int rs = (tid & 7) * 4;
    union { __half b[4]; unsigned long long u; } H;
#pragma unroll
    for (int j = 0; j < 4; ++j)
        H.b[j] = __float2half(tile[(rs + j) * 33 + cl]);
    const long long basee = (long long)(c0 + cl) * 2 * R + (r0 + rs);
    *(unsigned long long*)(Dp + basee)     = H.u;
    *(unsigned long long*)(Dp + basee + R) = H.u;
}

// ---------------------------------------------------------------------------
// Fused softmax + split: fp32 row [1024] -> fp16 [2*1024] (hi,lo).
// ---------------------------------------------------------------------------
__global__ __launch_bounds__(256) void softmax_split(
    const float* __restrict__ s, __half* __restrict__ dst)
{
    const long long row = blockIdx.x;
    const float* p = s + row * 1024;
    const int tid = threadIdx.x;

    float4 v = *(const float4*)(p + tid * 4);
    __shared__ float red[8];

    float m = fmaxf(fmaxf(v.x, v.y), fmaxf(v.z, v.w));
#pragma unroll
    for (int o = 16; o > 0; o >>= 1) m = fmaxf(m, __shfl_xor_sync(0xffffffffu, m, o));
    if ((tid & 31) == 0) red[tid >> 5] = m;
    __syncthreads();
    float bm = red[0];
#pragma unroll
    for (int i = 1; i < 8; ++i) bm = fmaxf(bm, red[i]);
    __syncthreads();

    v.x = __expf(v.x - bm); v.y = __expf(v.y - bm);
    v.z = __expf(v.z - bm); v.w = __expf(v.w - bm);
    float sum = v.x + v.y + v.z + v.w;
#pragma unroll
    for (int o = 16; o > 0; o >>= 1) sum += __shfl_xor_sync(0xffffffffu, sum, o);
    if ((tid & 31) == 0) red[tid >> 5] = sum;
    __syncthreads();
    float bs = red[0];
#pragma unroll
    for (int i = 1; i < 8; ++i) bs += red[i];

    const float inv = 1.0f / bs;
    v.x *= inv; v.y *= inv; v.z *= inv; v.w *= inv;

    uint32_t h0, l0, h1, l1;
    split2(v.x, v.y, h0, l0);
    split2(v.z, v.w, h1, l1);
    uint2 H = make_uint2(h0, h1);
    uint2 L = make_uint2(l0, l1);
    __half* d0 = dst + row * 2048 + tid * 4;
    *(uint2*)(d0)        = H;
    *(uint2*)(d0 + 1024) = L;
}

// ---------------------------------------------------------------------------
extern "C" void kernel_launch(void* const* d_in, const int* in_sizes, int n_in,
                              void* d_out, int out_size)
{
    const float* x   = (const float*)d_in[0];
    const float* enc = (const float*)d_in[1];
    const float* Wq  = (const float*)d_in[2];
    const float* bq  = (const float*)d_in[3];
    const float* Wk  = (const float*)d_in[4];
    const float* bk  = (const float*)d_in[5];
    const float* Wv  = (const float*)d_in[6];
    const float* bv  = (const float*)d_in[7];
    const float* Wp  = (const float*)d_in[8];
    const float* bp  = (const float*)d_in[9];
    float* out = (float*)d_out;

    float* scores;
    __half *xc, *encc, *qc, *kc, *vtc, *attnc, *wqt, *wkt, *wvt, *wpt;
    cudaGetSymbolAddress((void**)&scores, g_scores);
    cudaGetSymbolAddress((void**)&xc, g_xc);
    cudaGetSymbolAddress((void**)&encc, g_encc);
    cudaGetSymbolAddress((void**)&qc, g_qc);
    cudaGetSymbolAddress((void**)&kc, g_kc);
    cudaGetSymbolAddress((void**)&vtc, g_vtc);
    cudaGetSymbolAddress((void**)&attnc, g_attnc);
    cudaGetSymbolAddress((void**)&wqt, g_wqt);
    cudaGetSymbolAddress((void**)&wkt, g_wkt);
    cudaGetSymbolAddress((void**)&wvt, g_wvt);
    cudaGetSymbolAddress((void**)&wpt, g_wpt);

    cudaFuncSetAttribute(gemm_mma_nt,
                         cudaFuncAttributeMaxDynamicSharedMemorySize, DSMEM_BYTES);

    const int BT = Bb_ * T_;                 // 8192
    const float scale = 1.0f / sqrtf((float)Hh_);
    dim3 blk(256);

    // 1. Weight transposes+splits (hi,hi), one launch
    {
        dim3 g(E_ / 32, E_ / 32, 4);
        convT_split_w<<<g, blk>>>(Wq, Wk, Wv, Wp, wqt, wkt, wvt, wpt, E_, Hh_);
    }

    // 2. x & enc splits (hi,lo), one launch
    {
        long long t8 = (long long)BT * E_ / 8;
        dim3 g((unsigned)((t8 + 255) / 256), 1, 2);
        conv_split8_2<<<g, blk>>>(x, xc, enc, encc, E_, t8);
    }

    // 3. Q+K projections merged (z selects); V^T by GEMM (row bias)
    {
        dim3 gqk(Hh_ / 128, BT / 128, 2);
        gemm_mma_nt<<<gqk, blk, DSMEM_BYTES>>>(xc, wqt, bq, nullptr, qc, 1, 0, 1,
                                               encc, wkt, bk, kc,
                                               BT, Hh_, 2 * E_, 1.0f, 0, 0, 0);
        // v^T[b]: [Hh, S] = wvt([h,h]) x encc[b]([h,l]); (hi,hi) split -> vtc
        dim3 gv(S_ / 128, Hh_ / 128, Bb_);
        gemm_mma_nt<<<gv, blk, DSMEM_BYTES>>>(wvt, encc, bv, nullptr, vtc, 2, 1, 0,
                                              nullptr, nullptr, nullptr, nullptr,
                                              Hh_, S_, 2 * E_, 1.0f,
                                              0, (long long)S_ * 2 * E_,
                                              (long long)Hh_ * 2 * S_);
    }

    // 4. scores[b] = q[b] k[b]^T * scale  (fp32)
    {
        dim3 g(S_ / 128, T_ / 128, Bb_);
        gemm_mma_nt<<<g, blk, DSMEM_BYTES>>>(qc, kc, nullptr, scores, nullptr, 0, 0, 0,
                                             nullptr, nullptr, nullptr, nullptr,
                                             T_, S_, 2 * Hh_, scale,
                                             (long long)T_ * 2 * Hh_,
                                             (long long)S_ * 2 * Hh_,
                                             (long long)T_ * S_);
    }

    // 5. softmax + split (hi,lo) -> attnc
    softmax_split<<<BT, blk>>>(scores, attnc);

    // 6. attnout[b] = attn[b] @ v[b]; split (hi,lo) -> xc
    {
        dim3 g(Hh_ / 128, T_ / 128, Bb_);
        gemm_mma_nt<<<g, blk, DSMEM_BYTES>>>(attnc, vtc, nullptr, nullptr, xc, 1, 0, 0,
                                             nullptr, nullptr, nullptr, nullptr,
                                             T_, Hh_, 2 * S_, 1.0f,
                                             (long long)T_ * 2 * S_,
                                             (long long)Hh_ * 2 * S_,
                                             (long long)T_ * 2 * Hh_);
    }

    // 7. out = attnout @ Wp + bp  (fp32)
    {
        dim3 g(E_ / 128, BT / 128, 1);
        gemm_mma_nt<<<g, blk, DSMEM_BYTES>>>(xc, wpt, bp, out, nullptr, 0, 0, 0,
                                             nullptr, nullptr, nullptr, nullptr,
                                             BT, E_, 2 * Hh_, 1.0f, 0, 0, 0);
    }
}